// round 7
// baseline (speedup 1.0000x reference)
#include <cuda_runtime.h>
#include <cuda_bf16.h>
#include <math.h>
#include <cstdint>

// Problem constants
constexpr int Bc = 8;
constexpr int Sc = 512;
constexpr int Ec = 1024;
constexpr int Hc = 16;
constexpr int Dc = 64;
constexpr int Mrows = Bc * Sc;   // 4096

// Scratch (static device arrays: allocation-free)
__device__ float g_Q[(size_t)Mrows * Ec];
__device__ float g_K[(size_t)Mrows * Ec];
__device__ float g_V[(size_t)Mrows * Ec];
__device__ float g_ctx[(size_t)Mrows * Ec];
__device__ float g_cxq[(size_t)Mrows * Ec];
__device__ float g_cxk[(size_t)Mrows * Ec];
__device__ float g_cxv[(size_t)Mrows * Ec];
__device__ float g_cwq[(size_t)Ec * Ec];
__device__ float g_cwk[(size_t)Ec * Ec];
__device__ float g_cwv[(size_t)Ec * Ec];
__device__ float g_cwo[(size_t)Ec * Ec];

// ---------------------------------------------------------------------------
// helpers
// ---------------------------------------------------------------------------
__device__ __forceinline__ uint32_t s2u(const void* p) {
    uint32_t a;
    asm("{ .reg .u64 t; cvta.to.shared.u64 t, %1; cvt.u32.u64 %0, t; }"
        : "=r"(a) : "l"(p));
    return a;
}

__device__ __forceinline__ void cp_async16(uint32_t saddr, const void* gaddr) {
    asm volatile("cp.async.cg.shared.global [%0], [%1], 16;" :: "r"(saddr), "l"(gaddr));
}
#define CP_COMMIT() asm volatile("cp.async.commit_group;" ::: "memory")
#define CP_WAIT(n)  asm volatile("cp.async.wait_group %0;" :: "n"(n) : "memory")

__device__ __forceinline__ float tf32r(float f) {
    uint32_t u;
    asm("cvt.rna.tf32.f32 %0, %1;" : "=r"(u) : "f"(f));
    return __uint_as_float(u);
}

__device__ __forceinline__ void mma_tf32(float* d, const uint32_t* a, const uint32_t* b) {
    asm volatile(
        "mma.sync.aligned.m16n8k8.row.col.f32.tf32.tf32.f32 "
        "{%0,%1,%2,%3}, {%4,%5,%6,%7}, {%8,%9}, {%0,%1,%2,%3};"
        : "+f"(d[0]), "+f"(d[1]), "+f"(d[2]), "+f"(d[3])
        : "r"(a[0]), "r"(a[1]), "r"(a[2]), "r"(a[3]), "r"(b[0]), "r"(b[1]));
}

__device__ __forceinline__ void ldsm4(uint32_t* r, const void* smem_ptr) {
    uint32_t a = s2u(smem_ptr);
    asm volatile("ldmatrix.sync.aligned.m8n8.x4.shared.b16 {%0,%1,%2,%3}, [%4];"
                 : "=r"(r[0]), "=r"(r[1]), "=r"(r[2]), "=r"(r[3]) : "r"(a));
}

// ---------------------------------------------------------------------------
// fused fp32 -> tf32 pre-pass for all 7 tensors (grid.y selects)
// ---------------------------------------------------------------------------
__global__ void cvt_all(const float* i0, const float* i1, const float* i2,
                        const float* i3, const float* i4, const float* i5,
                        const float* i6,
                        float* o0, float* o1, float* o2, float* o3,
                        float* o4, float* o5, float* o6,
                        int nx4, int nw4) {
    const int y = blockIdx.y;
    const float* in;
    float* out;
    int n4;
    switch (y) {
        case 0: in = i0; out = o0; n4 = nx4; break;
        case 1: in = i1; out = o1; n4 = nx4; break;
        case 2: in = i2; out = o2; n4 = nx4; break;
        case 3: in = i3; out = o3; n4 = nw4; break;
        case 4: in = i4; out = o4; n4 = nw4; break;
        case 5: in = i5; out = o5; n4 = nw4; break;
        default: in = i6; out = o6; n4 = nw4; break;
    }
    int i = blockIdx.x * blockDim.x + threadIdx.x;
    if (i >= n4) return;
    float4 v = ((const float4*)in)[i];
    v.x = tf32r(v.x); v.y = tf32r(v.y); v.z = tf32r(v.z); v.w = tf32r(v.w);
    ((float4*)out)[i] = v;
}

// ---------------------------------------------------------------------------
// tf32 HMMA GEMM body. One barrier per chunk; exact wait_group semantics.
// ---------------------------------------------------------------------------
constexpr int BK = 32;
constexpr int PITCH = 36;
constexpr int STAGES = 3;
constexpr int TILE_F = 128 * PITCH;
constexpr int STAGE_F = 2 * TILE_F;
constexpr int NCH = Ec / BK;
constexpr int SMEM_GEMM = STAGES * STAGE_F * 4;   // 110592 B

__device__ __forceinline__
void gemm_body(const float* __restrict__ A, const float* __restrict__ W,
               const float* __restrict__ bias, float* __restrict__ out,
               int scatter, int round_out, float* sm)
{
    const int tid = threadIdx.x;
    const int lane = tid & 31;
    const int wid = tid >> 5;
    const int warp_m = wid >> 2;
    const int warp_n = wid & 3;
    const int g = lane >> 2;
    const int t = lane & 3;
    const int m0 = blockIdx.y * 128;
    const int n0 = blockIdx.x * 128;

    const int aRow = warp_m * 64 + ((lane >> 3) & 1) * 8 + (lane & 7);
    const int aCol = (lane >> 4) * 4;
    const int bRow = warp_n * 32 + (lane >> 4) * 8 + (lane & 7);
    const int bCol = ((lane >> 3) & 1) * 4;

    float d[4][4][4];
    #pragma unroll
    for (int i = 0; i < 4; i++)
        #pragma unroll
        for (int j = 0; j < 4; j++)
            #pragma unroll
            for (int k = 0; k < 4; k++) d[i][j][k] = 0.f;

    const float* gA0 = A + (size_t)m0 * Ec;
    const float* gW0 = W + (size_t)n0 * Ec;

    auto load_stage = [&](int c) {
        float* As = sm + (c % STAGES) * STAGE_F;
        float* Bs = As + TILE_F;
        const float* gA = gA0 + c * BK;
        const float* gW = gW0 + c * BK;
        #pragma unroll
        for (int i = 0; i < 4; i++) {
            const int idx = tid + i * 256;
            const int row = idx >> 3, seg = idx & 7;
            cp_async16(s2u(As + row * PITCH + seg * 4),
                       gA + (size_t)row * Ec + seg * 4);
            cp_async16(s2u(Bs + row * PITCH + seg * 4),
                       gW + (size_t)row * Ec + seg * 4);
        }
    };

    load_stage(0); CP_COMMIT();
    load_stage(1); CP_COMMIT();

    for (int c = 0; c < NCH; c++) {
        // groups committed so far: min(c+2, NCH). Need group c complete.
        if (c + 1 < NCH) { CP_WAIT(1); } else { CP_WAIT(0); }
        __syncthreads();   // single barrier: data ready + prev chunk consumed

        if (c + 2 < NCH) { load_stage(c + 2); CP_COMMIT(); }

        const float* As = sm + (c % STAGES) * STAGE_F;
        const float* Bs = As + TILE_F;

        #pragma unroll
        for (int ks = 0; ks < 4; ks++) {
            uint32_t a[4][4], b[4][2];
            #pragma unroll
            for (int mt = 0; mt < 4; mt++)
                ldsm4(a[mt], As + (aRow + mt * 16) * PITCH + ks * 8 + aCol);
            ldsm4(&b[0][0], Bs + bRow * PITCH + ks * 8 + bCol);
            ldsm4(&b[2][0], Bs + (bRow + 16) * PITCH + ks * 8 + bCol);
            #pragma unroll
            for (int mt = 0; mt < 4; mt++)
                #pragma unroll
                for (int nt = 0; nt < 4; nt++)
                    mma_tf32(d[mt][nt], a[mt], b[nt]);
        }
    }

    #pragma unroll
    for (int mt = 0; mt < 4; mt++) {
        #pragma unroll
        for (int nt = 0; nt < 4; nt++) {
            const int n = n0 + warp_n * 32 + nt * 8 + 2 * t;
            const float b0 = bias[n], b1 = bias[n + 1];
            #pragma unroll
            for (int half = 0; half < 2; half++) {
                const int m = m0 + warp_m * 64 + mt * 16 + g + half * 8;
                float2 v;
                v.x = d[mt][nt][half * 2 + 0] + b0;
                v.y = d[mt][nt][half * 2 + 1] + b1;
                if (round_out) { v.x = tf32r(v.x); v.y = tf32r(v.y); }
                if (scatter == 0) {
                    const int bb = m >> 9, ss = m & (Sc - 1);
                    const int hh = n >> 6, dd = n & (Dc - 1);
                    *(float2*)&out[((((size_t)bb * Hc + hh) * Sc + ss) << 6) + dd] = v;
                } else {
                    *(float2*)&out[(size_t)m * Ec + n] = v;
                }
            }
        }
    }
}

__global__ __launch_bounds__(256, 2)
void gemm_qkv(const float* A0, const float* A1, const float* A2,
              const float* W0, const float* W1, const float* W2,
              const float* b0, const float* b1, const float* b2,
              float* o0, float* o1, float* o2)
{
    extern __shared__ float sm[];
    const int z = blockIdx.z;
    const float* A = z == 0 ? A0 : z == 1 ? A1 : A2;
    const float* W = z == 0 ? W0 : z == 1 ? W1 : W2;
    const float* bi = z == 0 ? b0 : z == 1 ? b1 : b2;
    float* out = z == 0 ? o0 : z == 1 ? o1 : o2;
    gemm_body(A, W, bi, out, 0, z == 2 ? 1 : 0, sm);
}

__global__ __launch_bounds__(256, 2)
void gemm_out(const float* __restrict__ A, const float* __restrict__ W,
              const float* __restrict__ bias, float* __restrict__ out)
{
    extern __shared__ float sm[];
    gemm_body(A, W, bias, out, 1, 0, sm);
}

// ---------------------------------------------------------------------------
// RoPE + L2 norm; Q additionally scaled by temperature. tf32-rounded output.
// ---------------------------------------------------------------------------
__global__ void rope_l2(float* __restrict__ TQ, float* __restrict__ TK,
                        const float* __restrict__ cosT,
                        const float* __restrict__ sinT,
                        const float* __restrict__ tempPtr)
{
    float* T = blockIdx.y ? TK : TQ;
    const float scale = blockIdx.y ? 1.0f : *tempPtr;
    const int row = blockIdx.x * 8 + (threadIdx.x >> 5);
    const int lane = threadIdx.x & 31;
    const int s = row & (Sc - 1);

    float2* p = (float2*)(T + (size_t)row * Dc);
    float2 v = p[lane];
    const float c = cosT[s * 32 + lane];
    const float sn = sinT[s * 32 + lane];
    const float r0 = v.x * c - v.y * sn;
    const float r1 = v.x * sn + v.y * c;

    float ss = r0 * r0 + r1 * r1;
    #pragma unroll
    for (int o = 16; o; o >>= 1) ss += __shfl_xor_sync(0xffffffffu, ss, o);
    const float inv = scale / fmaxf(sqrtf(ss), 1e-12f);

    p[lane] = make_float2(tf32r(r0 * inv), tf32r(r1 * inv));
}

// ---------------------------------------------------------------------------
// Flash attention: 128 threads, warp owns 16 q-rows. Online softmax; K double-
// buffered; V transposed in smem; probs staged through warp-private smem
// (STS.64 + ldmatrix) instead of shuffles.
// smem: QVt[64][68] | Kb0 | Kb1 | P[4][16][68]  -> 69632 B
// ---------------------------------------------------------------------------
constexpr int AP = 68;
constexpr int FLASH_TILE = 64 * AP;                 // 4352 floats
constexpr int SMEM_FLASH = 4 * FLASH_TILE * 4;      // 69632 B

__global__ __launch_bounds__(128, 2)
void attn_flash(const float* __restrict__ Q,
                const float* __restrict__ K,
                const float* __restrict__ V,
                float* __restrict__ ctx)
{
    extern __shared__ float smf[];
    float* QVt = smf;                     // Q tile, later V^T [d][key]
    float* Kb0 = smf + FLASH_TILE;
    float* Kb1 = smf + 2 * FLASH_TILE;
    float* Pw  = smf + 3 * FLASH_TILE;    // per-warp prob tiles [16][AP]

    const int tid = threadIdx.x;
    const int lane = tid & 31;
    const int warp = tid >> 5;
    const int g = lane >> 2;
    const int t = lane & 3;
    const int qt = blockIdx.x;
    const int bh = blockIdx.y;
    const int bb = bh >> 4;
    const int hh = bh & 15;
    const size_t head_off = (size_t)bh * Sc * Dc;

    const int lr8 = ((lane >> 3) & 1) * 8 + (lane & 7);
    const int lc4 = (lane >> 4) * 4;
    const int br16 = (lane >> 4) * 8 + (lane & 7);
    const int bc4 = ((lane >> 3) & 1) * 4;

    const int vd4 = tid >> 3;
    const int vr0 = tid & 7;

    float* P = Pw + warp * 16 * AP;

    // ---- load Q tile [64][64] into smem ----
    {
        const float4* src = (const float4*)(Q + head_off + (size_t)qt * 64 * Dc);
        for (int i = tid; i < 1024; i += 128) {
            const int r = i >> 4, c4 = i & 15;
            *(float4*)&QVt[r * AP + c4 * 4] = src[i];
        }
    }
    __syncthreads();

    uint32_t qf[8][4];
    #pragma unroll
    for (int ks = 0; ks < 8; ks++)
        ldsm4(qf[ks], QVt + (warp * 16 + lr8) * AP + ks * 8 + lc4);

    float run_m0 = -1e30f, run_m1 = -1e30f;
    float run_s0 = 0.f, run_s1 = 0.f;
    float oacc[8][4];
    #pragma unroll
    for (int j = 0; j < 8; j++)
        #pragma unroll
        for (int k = 0; k < 4; k++) oacc[j][k] = 0.f;

    // prefetch K chunk 0
    {
        const float* gK = K + head_off;
        #pragma unroll
        for (int i = 0; i < 8; i++) {
            const int idx = tid + i * 128;
            const int r = idx >> 4, seg = idx & 15;
            cp_async16(s2u(Kb0 + r * AP + seg * 4), gK + (size_t)r * Dc + seg * 4);
        }
        CP_COMMIT();
    }

    const uint32_t fullm = 0xffffffffu;

    for (int kt = 0; kt < 8; kt++) {
        float* Kc = (kt & 1) ? Kb1 : Kb0;
        float* Kn = (kt & 1) ? Kb0 : Kb1;

        // prefetch V chunk into registers
        float4 vrg[8];
        {
            const float4* gV = (const float4*)(V + head_off + (size_t)kt * 64 * Dc);
            #pragma unroll
            for (int p = 0; p < 8; p++)
                vrg[p] = gV[(vr0 + 8 * p) * 16 + vd4];
        }

        CP_WAIT(0);
        __syncthreads();

        // transpose-store V into QVt: QVt[d][key]
        #pragma unroll
        for (int p = 0; p < 8; p++) {
            const int key = vr0 + 8 * p;
            QVt[(vd4 * 4 + 0) * AP + key] = vrg[p].x;
            QVt[(vd4 * 4 + 1) * AP + key] = vrg[p].y;
            QVt[(vd4 * 4 + 2) * AP + key] = vrg[p].z;
            QVt[(vd4 * 4 + 3) * AP + key] = vrg[p].w;
        }

        if (kt < 7) {
            const float* gK = K + head_off + (size_t)(kt + 1) * 64 * Dc;
            #pragma unroll
            for (int i = 0; i < 8; i++) {
                const int idx = tid + i * 128;
                const int r = idx >> 4, seg = idx & 15;
                cp_async16(s2u(Kn + r * AP + seg * 4), gK + (size_t)r * Dc + seg * 4);
            }
            CP_COMMIT();
        }

        // ---- QK^T ----
        float s[8][4];
        #pragma unroll
        for (int j = 0; j < 8; j++)
            #pragma unroll
            for (int k = 0; k < 4; k++) s[j][k] = 0.f;

        #pragma unroll
        for (int ks = 0; ks < 8; ks++) {
            uint32_t b[4][4];
            #pragma unroll
            for (int jj = 0; jj < 4; jj++)
                ldsm4(b[jj], Kc + (jj * 16 + br16) * AP + ks * 8 + bc4);
            #pragma unroll
            for (int jj = 0; jj < 4; jj++) {
                mma_tf32(s[2 * jj + 0], qf[ks], &b[jj][0]);
                mma_tf32(s[2 * jj + 1], qf[ks], &b[jj][2]);
            }
        }

        // ---- online softmax (temp already folded into Q) ----
        float cm0 = -1e30f, cm1 = -1e30f;
        #pragma unroll
        for (int j = 0; j < 8; j++) {
            cm0 = fmaxf(cm0, fmaxf(s[j][0], s[j][1]));
            cm1 = fmaxf(cm1, fmaxf(s[j][2], s[j][3]));
        }
        cm0 = fmaxf(cm0, __shfl_xor_sync(fullm, cm0, 1));
        cm0 = fmaxf(cm0, __shfl_xor_sync(fullm, cm0, 2));
        cm1 = fmaxf(cm1, __shfl_xor_sync(fullm, cm1, 1));
        cm1 = fmaxf(cm1, __shfl_xor_sync(fullm, cm1, 2));

        const float nm0 = fmaxf(run_m0, cm0);
        const float nm1 = fmaxf(run_m1, cm1);
        const float sc0 = __expf(run_m0 - nm0);
        const float sc1 = __expf(run_m1 - nm1);
        run_m0 = nm0; run_m1 = nm1;

        float ps0 = 0.f, ps1 = 0.f;
        #pragma unroll
        for (int j = 0; j < 8; j++) {
            float p0 = __expf(s[j][0] - nm0);
            float p1 = __expf(s[j][1] - nm0);
            float p2 = __expf(s[j][2] - nm1);
            float p3 = __expf(s[j][3] - nm1);
            ps0 += p0 + p1; ps1 += p2 + p3;
            s[j][0] = tf32r(p0); s[j][1] = tf32r(p1);
            s[j][2] = tf32r(p2); s[j][3] = tf32r(p3);
        }
        ps0 += __shfl_xor_sync(fullm, ps0, 1);
        ps0 += __shfl_xor_sync(fullm, ps0, 2);
        ps1 += __shfl_xor_sync(fullm, ps1, 1);
        ps1 += __shfl_xor_sync(fullm, ps1, 2);
        run_s0 = run_s0 * sc0 + ps0;
        run_s1 = run_s1 * sc1 + ps1;

        #pragma unroll
        for (int j = 0; j < 8; j++) {
            oacc[j][0] *= sc0; oacc[j][1] *= sc0;
            oacc[j][2] *= sc1; oacc[j][3] *= sc1;
        }

        // stage probs into warp-private P tile (C-frag layout -> [row][key])
        #pragma unroll
        for (int jj = 0; jj < 4; jj++) {
            *(float2*)&P[g * AP + jj * 16 + 2 * t]        = make_float2(s[2*jj][0],   s[2*jj][1]);
            *(float2*)&P[(g + 8) * AP + jj * 16 + 2 * t]  = make_float2(s[2*jj][2],   s[2*jj][3]);
            *(float2*)&P[g * AP + jj * 16 + 8 + 2 * t]       = make_float2(s[2*jj+1][0], s[2*jj+1][1]);
            *(float2*)&P[(g + 8) * AP + jj * 16 + 8 + 2 * t] = make_float2(s[2*jj+1][2], s[2*jj+1][3]);
        }

        __syncthreads();     // V^T stores visible (also covers P per-warp)

        // ---- PV: P(16x64) @ V(64x64) via ldmatrix A-frags ----
        #pragma unroll
        for (int k8 = 0; k8 < 8; k8++) {
            uint32_t a[4];
            ldsm4(a, P + lr8 * AP + k8 * 8 + lc4);
            #pragma unroll
            for (int dj = 0; dj < 4; dj++) {
                uint32_t b[4];
                ldsm4(b, QVt + (dj * 16 + br16) * AP + k8 * 8 + bc4);
                mma_tf32(oacc[2 * dj + 0], a, &b[0]);
                mma_tf32(oacc[2 * dj + 1], a, &b[2]);
            }
        }
    }

    // ---- epilogue ----
    const float inv0 = 1.f / run_s0;
    const float inv1 = 1.f / run_s1;
    #pragma unroll
    for (int d8 = 0; d8 < 8; d8++) {
        const int dcol = d8 * 8 + 2 * t;
        {
            const int srow = qt * 64 + warp * 16 + g;
            float2 v;
            v.x = tf32r(oacc[d8][0] * inv0);
            v.y = tf32r(oacc[d8][1] * inv0);
            *(float2*)&ctx[((size_t)bb * Sc + srow) * Ec + hh * Dc + dcol] = v;
        }
        {
            const int srow = qt * 64 + warp * 16 + g + 8;
            float2 v;
            v.x = tf32r(oacc[d8][2] * inv1);
            v.y = tf32r(oacc[d8][3] * inv1);
            *(float2*)&ctx[((size_t)bb * Sc + srow) * Ec + hh * Dc + dcol] = v;
        }
    }
}

// ---------------------------------------------------------------------------
extern "C" void kernel_launch(void* const* d_in, const int* in_sizes, int n_in,
                              void* d_out, int out_size)
{
    const float* x_q  = (const float*)d_in[0];
    const float* x_k  = (const float*)d_in[1];
    const float* x_v  = (const float*)d_in[2];
    const float* Wq   = (const float*)d_in[3];
    const float* bq   = (const float*)d_in[4];
    const float* Wk   = (const float*)d_in[5];
    const float* bk   = (const float*)d_in[6];
    const float* Wv   = (const float*)d_in[7];
    const float* bv   = (const float*)d_in[8];
    const float* Wo   = (const float*)d_in[9];
    const float* bo   = (const float*)d_in[10];
    const float* temp = (const float*)d_in[11];
    const float* cosT = (const float*)d_in[12];
    const float* sinT = (const float*)d_in[13];
    float* out = (float*)d_out;

    float *pQ, *pK, *pV, *pC, *cxq, *cxk, *cxv, *cwq, *cwk, *cwv, *cwo;
    cudaGetSymbolAddress((void**)&pQ, g_Q);
    cudaGetSymbolAddress((void**)&pK, g_K);
    cudaGetSymbolAddress((void**)&pV, g_V);
    cudaGetSymbolAddress((void**)&pC, g_ctx);
    cudaGetSymbolAddress((void**)&cxq, g_cxq);
    cudaGetSymbolAddress((void**)&cxk, g_cxk);
    cudaGetSymbolAddress((void**)&cxv, g_cxv);
    cudaGetSymbolAddress((void**)&cwq, g_cwq);
    cudaGetSymbolAddress((void**)&cwk, g_cwk);
    cudaGetSymbolAddress((void**)&cwv, g_cwv);
    cudaGetSymbolAddress((void**)&cwo, g_cwo);

    cudaFuncSetAttribute(gemm_qkv,
                         cudaFuncAttributeMaxDynamicSharedMemorySize, SMEM_GEMM);
    cudaFuncSetAttribute(gemm_out,
                         cudaFuncAttributeMaxDynamicSharedMemorySize, SMEM_GEMM);
    cudaFuncSetAttribute(attn_flash,
                         cudaFuncAttributeMaxDynamicSharedMemorySize, SMEM_FLASH);

    const int nx4 = Mrows * Ec / 4;   // 1M
    const int nw4 = Ec * Ec / 4;      // 256K

    cvt_all<<<dim3((nx4 + 255) / 256, 7), 256>>>(
        x_q, x_k, x_v, Wq, Wk, Wv, Wo,
        cxq, cxk, cxv, cwq, cwk, cwv, cwo, nx4, nw4);

    gemm_qkv<<<dim3(Ec / 128, Mrows / 128, 3), 256, SMEM_GEMM>>>(
        cxq, cxk, cxv, cwq, cwk, cwv, bq, bk, bv, pQ, pK, pV);

    rope_l2<<<dim3((Bc * Hc * Sc) / 8, 2), 256>>>(pQ, pK, cosT, sinT, temp);

    attn_flash<<<dim3(8, Bc * Hc), 128, SMEM_FLASH>>>(pQ, pK, pV, pC);

    gemm_out<<<dim3(Ec / 128, Mrows / 128), 256, SMEM_GEMM>>>(pC, cwo, bo, out);
}

// round 8
// speedup vs baseline: 1.0743x; 1.0743x over previous
#include <cuda_runtime.h>
#include <cuda_bf16.h>
#include <math.h>
#include <cstdint>

// Problem constants
constexpr int Bc = 8;
constexpr int Sc = 512;
constexpr int Ec = 1024;
constexpr int Hc = 16;
constexpr int Dc = 64;
constexpr int Mrows = Bc * Sc;   // 4096

// Scratch (static device arrays: allocation-free)
__device__ float g_Q[(size_t)Mrows * Ec];
__device__ float g_K[(size_t)Mrows * Ec];
__device__ float g_V[(size_t)Mrows * Ec];
__device__ float g_ctx[(size_t)Mrows * Ec];
__device__ float g_cxq[(size_t)Mrows * Ec];
__device__ float g_cxk[(size_t)Mrows * Ec];
__device__ float g_cxv[(size_t)Mrows * Ec];
__device__ float g_cwq[(size_t)Ec * Ec];
__device__ float g_cwk[(size_t)Ec * Ec];
__device__ float g_cwv[(size_t)Ec * Ec];
__device__ float g_cwo[(size_t)Ec * Ec];

// ---------------------------------------------------------------------------
// helpers
// ---------------------------------------------------------------------------
__device__ __forceinline__ uint32_t s2u(const void* p) {
    uint32_t a;
    asm("{ .reg .u64 t; cvta.to.shared.u64 t, %1; cvt.u32.u64 %0, t; }"
        : "=r"(a) : "l"(p));
    return a;
}

__device__ __forceinline__ void cp_async16(uint32_t saddr, const void* gaddr) {
    asm volatile("cp.async.cg.shared.global [%0], [%1], 16;" :: "r"(saddr), "l"(gaddr));
}
#define CP_COMMIT() asm volatile("cp.async.commit_group;" ::: "memory")
#define CP_WAIT(n)  asm volatile("cp.async.wait_group %0;" :: "n"(n) : "memory")

__device__ __forceinline__ float tf32r(float f) {
    uint32_t u;
    asm("cvt.rna.tf32.f32 %0, %1;" : "=r"(u) : "f"(f));
    return __uint_as_float(u);
}

__device__ __forceinline__ void mma_tf32(float* d, const uint32_t* a, const uint32_t* b) {
    asm volatile(
        "mma.sync.aligned.m16n8k8.row.col.f32.tf32.tf32.f32 "
        "{%0,%1,%2,%3}, {%4,%5,%6,%7}, {%8,%9}, {%0,%1,%2,%3};"
        : "+f"(d[0]), "+f"(d[1]), "+f"(d[2]), "+f"(d[3])
        : "r"(a[0]), "r"(a[1]), "r"(a[2]), "r"(a[3]), "r"(b[0]), "r"(b[1]));
}

__device__ __forceinline__ void ldsm4(uint32_t* r, const void* smem_ptr) {
    uint32_t a = s2u(smem_ptr);
    asm volatile("ldmatrix.sync.aligned.m8n8.x4.shared.b16 {%0,%1,%2,%3}, [%4];"
                 : "=r"(r[0]), "=r"(r[1]), "=r"(r[2]), "=r"(r[3]) : "r"(a));
}

// ---------------------------------------------------------------------------
// fused fp32 -> tf32 pre-pass for all 7 tensors (grid.y selects)
// ---------------------------------------------------------------------------
__global__ void cvt_all(const float* i0, const float* i1, const float* i2,
                        const float* i3, const float* i4, const float* i5,
                        const float* i6,
                        float* o0, float* o1, float* o2, float* o3,
                        float* o4, float* o5, float* o6,
                        int nx4, int nw4) {
    const int y = blockIdx.y;
    const float* in;
    float* out;
    int n4;
    switch (y) {
        case 0: in = i0; out = o0; n4 = nx4; break;
        case 1: in = i1; out = o1; n4 = nx4; break;
        case 2: in = i2; out = o2; n4 = nx4; break;
        case 3: in = i3; out = o3; n4 = nw4; break;
        case 4: in = i4; out = o4; n4 = nw4; break;
        case 5: in = i5; out = o5; n4 = nw4; break;
        default: in = i6; out = o6; n4 = nw4; break;
    }
    int i = blockIdx.x * blockDim.x + threadIdx.x;
    if (i >= n4) return;
    float4 v = ((const float4*)in)[i];
    v.x = tf32r(v.x); v.y = tf32r(v.y); v.z = tf32r(v.z); v.w = tf32r(v.w);
    ((float4*)out)[i] = v;
}

// ---------------------------------------------------------------------------
// tf32 HMMA GEMM body (R7: single barrier per chunk)
// ---------------------------------------------------------------------------
constexpr int BK = 32;
constexpr int PITCH = 36;
constexpr int STAGES = 3;
constexpr int TILE_F = 128 * PITCH;
constexpr int STAGE_F = 2 * TILE_F;
constexpr int NCH = Ec / BK;
constexpr int SMEM_GEMM = STAGES * STAGE_F * 4;   // 110592 B

__device__ __forceinline__
void gemm_body(const float* __restrict__ A, const float* __restrict__ W,
               const float* __restrict__ bias, float* __restrict__ out,
               int scatter, int round_out, float* sm)
{
    const int tid = threadIdx.x;
    const int lane = tid & 31;
    const int wid = tid >> 5;
    const int warp_m = wid >> 2;
    const int warp_n = wid & 3;
    const int g = lane >> 2;
    const int t = lane & 3;
    const int m0 = blockIdx.y * 128;
    const int n0 = blockIdx.x * 128;

    const int aRow = warp_m * 64 + ((lane >> 3) & 1) * 8 + (lane & 7);
    const int aCol = (lane >> 4) * 4;
    const int bRow = warp_n * 32 + (lane >> 4) * 8 + (lane & 7);
    const int bCol = ((lane >> 3) & 1) * 4;

    float d[4][4][4];
    #pragma unroll
    for (int i = 0; i < 4; i++)
        #pragma unroll
        for (int j = 0; j < 4; j++)
            #pragma unroll
            for (int k = 0; k < 4; k++) d[i][j][k] = 0.f;

    const float* gA0 = A + (size_t)m0 * Ec;
    const float* gW0 = W + (size_t)n0 * Ec;

    auto load_stage = [&](int c) {
        float* As = sm + (c % STAGES) * STAGE_F;
        float* Bs = As + TILE_F;
        const float* gA = gA0 + c * BK;
        const float* gW = gW0 + c * BK;
        #pragma unroll
        for (int i = 0; i < 4; i++) {
            const int idx = tid + i * 256;
            const int row = idx >> 3, seg = idx & 7;
            cp_async16(s2u(As + row * PITCH + seg * 4),
                       gA + (size_t)row * Ec + seg * 4);
            cp_async16(s2u(Bs + row * PITCH + seg * 4),
                       gW + (size_t)row * Ec + seg * 4);
        }
    };

    load_stage(0); CP_COMMIT();
    load_stage(1); CP_COMMIT();

    for (int c = 0; c < NCH; c++) {
        if (c + 1 < NCH) { CP_WAIT(1); } else { CP_WAIT(0); }
        __syncthreads();

        if (c + 2 < NCH) { load_stage(c + 2); CP_COMMIT(); }

        const float* As = sm + (c % STAGES) * STAGE_F;
        const float* Bs = As + TILE_F;

        #pragma unroll
        for (int ks = 0; ks < 4; ks++) {
            uint32_t a[4][4], b[4][2];
            #pragma unroll
            for (int mt = 0; mt < 4; mt++)
                ldsm4(a[mt], As + (aRow + mt * 16) * PITCH + ks * 8 + aCol);
            ldsm4(&b[0][0], Bs + bRow * PITCH + ks * 8 + bCol);
            ldsm4(&b[2][0], Bs + (bRow + 16) * PITCH + ks * 8 + bCol);
            #pragma unroll
            for (int mt = 0; mt < 4; mt++)
                #pragma unroll
                for (int nt = 0; nt < 4; nt++)
                    mma_tf32(d[mt][nt], a[mt], b[nt]);
        }
    }

    #pragma unroll
    for (int mt = 0; mt < 4; mt++) {
        #pragma unroll
        for (int nt = 0; nt < 4; nt++) {
            const int n = n0 + warp_n * 32 + nt * 8 + 2 * t;
            const float b0 = bias[n], b1 = bias[n + 1];
            #pragma unroll
            for (int half = 0; half < 2; half++) {
                const int m = m0 + warp_m * 64 + mt * 16 + g + half * 8;
                float2 v;
                v.x = d[mt][nt][half * 2 + 0] + b0;
                v.y = d[mt][nt][half * 2 + 1] + b1;
                if (round_out) { v.x = tf32r(v.x); v.y = tf32r(v.y); }
                if (scatter == 0) {
                    const int bb = m >> 9, ss = m & (Sc - 1);
                    const int hh = n >> 6, dd = n & (Dc - 1);
                    *(float2*)&out[((((size_t)bb * Hc + hh) * Sc + ss) << 6) + dd] = v;
                } else {
                    *(float2*)&out[(size_t)m * Ec + n] = v;
                }
            }
        }
    }
}

__global__ __launch_bounds__(256, 2)
void gemm_qkv(const float* A0, const float* A1, const float* A2,
              const float* W0, const float* W1, const float* W2,
              const float* b0, const float* b1, const float* b2,
              float* o0, float* o1, float* o2)
{
    extern __shared__ float sm[];
    const int z = blockIdx.z;
    const float* A = z == 0 ? A0 : z == 1 ? A1 : A2;
    const float* W = z == 0 ? W0 : z == 1 ? W1 : W2;
    const float* bi = z == 0 ? b0 : z == 1 ? b1 : b2;
    float* out = z == 0 ? o0 : z == 1 ? o1 : o2;
    gemm_body(A, W, bi, out, 0, z == 2 ? 1 : 0, sm);
}

__global__ __launch_bounds__(256, 2)
void gemm_out(const float* __restrict__ A, const float* __restrict__ W,
              const float* __restrict__ bias, float* __restrict__ out)
{
    extern __shared__ float sm[];
    gemm_body(A, W, bias, out, 1, 0, sm);
}

// ---------------------------------------------------------------------------
// RoPE + L2 norm; Q scaled by temperature. tf32-rounded output.
// ---------------------------------------------------------------------------
__global__ void rope_l2(float* __restrict__ TQ, float* __restrict__ TK,
                        const float* __restrict__ cosT,
                        const float* __restrict__ sinT,
                        const float* __restrict__ tempPtr)
{
    float* T = blockIdx.y ? TK : TQ;
    const float scale = blockIdx.y ? 1.0f : *tempPtr;
    const int row = blockIdx.x * 8 + (threadIdx.x >> 5);
    const int lane = threadIdx.x & 31;
    const int s = row & (Sc - 1);

    float2* p = (float2*)(T + (size_t)row * Dc);
    float2 v = p[lane];
    const float c = cosT[s * 32 + lane];
    const float sn = sinT[s * 32 + lane];
    const float r0 = v.x * c - v.y * sn;
    const float r1 = v.x * sn + v.y * c;

    float ss = r0 * r0 + r1 * r1;
    #pragma unroll
    for (int o = 16; o; o >>= 1) ss += __shfl_xor_sync(0xffffffffu, ss, o);
    const float inv = scale / fmaxf(sqrtf(ss), 1e-12f);

    p[lane] = make_float2(tf32r(r0 * inv), tf32r(r1 * inv));
}

// ---------------------------------------------------------------------------
// Flash attention v2: q-tile 128, 128 threads, warp owns 32 q-rows (2 m-tiles).
// K double-buffered cp.async; V cp.async -> smem transpose; shuffle prob
// permute (no P smem); Q frags re-read per chunk (low regs).
// smem: QT[128][68] | Kb0[64][68] | Kb1 | Vl[64][68] | VT[64][68] = 104448 B
// ---------------------------------------------------------------------------
constexpr int AP = 68;
constexpr int QT_F = 128 * AP;                     // 8704
constexpr int KV_F = 64 * AP;                      // 4352
constexpr int SMEM_FLASH = (QT_F + 4 * KV_F) * 4;  // 104448 B

__global__ __launch_bounds__(128, 2)
void attn_flash(const float* __restrict__ Q,
                const float* __restrict__ K,
                const float* __restrict__ V,
                float* __restrict__ ctx)
{
    extern __shared__ float smf[];
    float* QT  = smf;
    float* Kb0 = smf + QT_F;
    float* Kb1 = Kb0 + KV_F;
    float* Vl  = Kb1 + KV_F;
    float* VT  = Vl + KV_F;

    const int tid = threadIdx.x;
    const int lane = tid & 31;
    const int warp = tid >> 5;            // owns q-rows warp*32 .. +31
    const int g = lane >> 2;
    const int t = lane & 3;
    const int qt = blockIdx.x;            // 0..3 (128-row q tiles)
    const int bh = blockIdx.y;
    const int bb = bh >> 4;
    const int hh = bh & 15;
    const size_t head_off = (size_t)bh * Sc * Dc;

    const int lr8 = ((lane >> 3) & 1) * 8 + (lane & 7);
    const int lc4 = (lane >> 4) * 4;
    const int br16 = (lane >> 4) * 8 + (lane & 7);
    const int bc4 = ((lane >> 3) & 1) * 4;

    const int vd4 = tid >> 3;             // 0..15
    const int vr0 = tid & 7;              // 0..7

    // ---- load Q tile [128][64] ----
    {
        const float4* src = (const float4*)(Q + head_off + (size_t)qt * 128 * Dc);
        for (int i = tid; i < 2048; i += 128) {
            const int r = i >> 4, c4 = i & 15;
            *(float4*)&QT[r * AP + c4 * 4] = src[i];
        }
    }

    // ---- prefetch K/V chunk 0 ----
    {
        const float* gK = K + head_off;
        const float* gV = V + head_off;
        #pragma unroll
        for (int i = 0; i < 8; i++) {
            const int idx = tid + i * 128;
            const int r = idx >> 4, seg = idx & 15;
            cp_async16(s2u(Kb0 + r * AP + seg * 4), gK + (size_t)r * Dc + seg * 4);
            cp_async16(s2u(Vl + r * AP + seg * 4), gV + (size_t)r * Dc + seg * 4);
        }
        CP_COMMIT();
    }

    // online softmax state, per m-tile: lanes own rows g (0) and g+8 (1)
    float run_m[2][2] = {{-1e30f, -1e30f}, {-1e30f, -1e30f}};
    float run_s[2][2] = {{0.f, 0.f}, {0.f, 0.f}};
    float oacc[2][8][4];
    #pragma unroll
    for (int mt = 0; mt < 2; mt++)
        #pragma unroll
        for (int j = 0; j < 8; j++)
            #pragma unroll
            for (int k = 0; k < 4; k++) oacc[mt][j][k] = 0.f;

    const uint32_t fullm = 0xffffffffu;
    const int src0 = (lane & ~3) | (t >> 1);
    const int src1 = src0 + 2;
    const bool odd = (t & 1) != 0;

    for (int kt = 0; kt < 8; kt++) {
        float* Kc = (kt & 1) ? Kb1 : Kb0;
        float* Kn = (kt & 1) ? Kb0 : Kb1;

        CP_WAIT(0);
        __syncthreads();     // K/V chunk ready; prev PV reads of VT done

        // ---- transpose Vl[key][d] -> VT[d][key] ----
        #pragma unroll
        for (int p = 0; p < 8; p++) {
            const int key = vr0 + 8 * p;
            float4 v = *(const float4*)&Vl[key * AP + vd4 * 4];
            VT[(vd4 * 4 + 0) * AP + key] = v.x;
            VT[(vd4 * 4 + 1) * AP + key] = v.y;
            VT[(vd4 * 4 + 2) * AP + key] = v.z;
            VT[(vd4 * 4 + 3) * AP + key] = v.w;
        }
        __syncthreads();     // VT visible; Vl reads done -> safe to refill

        // ---- prefetch next K/V chunk ----
        if (kt < 7) {
            const float* gK = K + head_off + (size_t)(kt + 1) * 64 * Dc;
            const float* gV = V + head_off + (size_t)(kt + 1) * 64 * Dc;
            #pragma unroll
            for (int i = 0; i < 8; i++) {
                const int idx = tid + i * 128;
                const int r = idx >> 4, seg = idx & 15;
                cp_async16(s2u(Kn + r * AP + seg * 4), gK + (size_t)r * Dc + seg * 4);
                cp_async16(s2u(Vl + r * AP + seg * 4), gV + (size_t)r * Dc + seg * 4);
            }
            CP_COMMIT();
        }

        // ---- QK^T: 32 q-rows x 64 keys, Q frags re-read from smem ----
        float s[2][8][4];
        #pragma unroll
        for (int mt = 0; mt < 2; mt++)
            #pragma unroll
            for (int j = 0; j < 8; j++)
                #pragma unroll
                for (int k = 0; k < 4; k++) s[mt][j][k] = 0.f;

        #pragma unroll
        for (int ks = 0; ks < 8; ks++) {
            uint32_t a[2][4], b[4][4];
            #pragma unroll
            for (int mt = 0; mt < 2; mt++)
                ldsm4(a[mt], QT + (warp * 32 + mt * 16 + lr8) * AP + ks * 8 + lc4);
            #pragma unroll
            for (int jj = 0; jj < 4; jj++)
                ldsm4(b[jj], Kc + (jj * 16 + br16) * AP + ks * 8 + bc4);
            #pragma unroll
            for (int mt = 0; mt < 2; mt++)
                #pragma unroll
                for (int jj = 0; jj < 4; jj++) {
                    mma_tf32(s[mt][2 * jj + 0], a[mt], &b[jj][0]);
                    mma_tf32(s[mt][2 * jj + 1], a[mt], &b[jj][2]);
                }
        }

        // ---- online softmax per m-tile ----
        #pragma unroll
        for (int mt = 0; mt < 2; mt++) {
            float cm0 = -1e30f, cm1 = -1e30f;
            #pragma unroll
            for (int j = 0; j < 8; j++) {
                cm0 = fmaxf(cm0, fmaxf(s[mt][j][0], s[mt][j][1]));
                cm1 = fmaxf(cm1, fmaxf(s[mt][j][2], s[mt][j][3]));
            }
            cm0 = fmaxf(cm0, __shfl_xor_sync(fullm, cm0, 1));
            cm0 = fmaxf(cm0, __shfl_xor_sync(fullm, cm0, 2));
            cm1 = fmaxf(cm1, __shfl_xor_sync(fullm, cm1, 1));
            cm1 = fmaxf(cm1, __shfl_xor_sync(fullm, cm1, 2));

            const float nm0 = fmaxf(run_m[mt][0], cm0);
            const float nm1 = fmaxf(run_m[mt][1], cm1);
            const float sc0 = __expf(run_m[mt][0] - nm0);
            const float sc1 = __expf(run_m[mt][1] - nm1);
            run_m[mt][0] = nm0; run_m[mt][1] = nm1;

            float ps0 = 0.f, ps1 = 0.f;
            #pragma unroll
            for (int j = 0; j < 8; j++) {
                float p0 = __expf(s[mt][j][0] - nm0);
                float p1 = __expf(s[mt][j][1] - nm0);
                float p2 = __expf(s[mt][j][2] - nm1);
                float p3 = __expf(s[mt][j][3] - nm1);
                ps0 += p0 + p1; ps1 += p2 + p3;
                s[mt][j][0] = tf32r(p0); s[mt][j][1] = tf32r(p1);
                s[mt][j][2] = tf32r(p2); s[mt][j][3] = tf32r(p3);
            }
            ps0 += __shfl_xor_sync(fullm, ps0, 1);
            ps0 += __shfl_xor_sync(fullm, ps0, 2);
            ps1 += __shfl_xor_sync(fullm, ps1, 1);
            ps1 += __shfl_xor_sync(fullm, ps1, 2);
            run_s[mt][0] = run_s[mt][0] * sc0 + ps0;
            run_s[mt][1] = run_s[mt][1] * sc1 + ps1;

            #pragma unroll
            for (int j = 0; j < 8; j++) {
                oacc[mt][j][0] *= sc0; oacc[mt][j][1] *= sc0;
                oacc[mt][j][2] *= sc1; oacc[mt][j][3] *= sc1;
            }
        }

        // ---- PV: shuffle-permute probs; V^T frags shared across m-tiles ----
        #pragma unroll
        for (int k8 = 0; k8 < 8; k8++) {
            uint32_t a[2][4];
            #pragma unroll
            for (int mt = 0; mt < 2; mt++) {
                float v00 = __shfl_sync(fullm, s[mt][k8][0], src0);
                float v01 = __shfl_sync(fullm, s[mt][k8][1], src0);
                float v02 = __shfl_sync(fullm, s[mt][k8][2], src0);
                float v03 = __shfl_sync(fullm, s[mt][k8][3], src0);
                float v10 = __shfl_sync(fullm, s[mt][k8][0], src1);
                float v11 = __shfl_sync(fullm, s[mt][k8][1], src1);
                float v12 = __shfl_sync(fullm, s[mt][k8][2], src1);
                float v13 = __shfl_sync(fullm, s[mt][k8][3], src1);
                a[mt][0] = __float_as_uint(odd ? v01 : v00);
                a[mt][1] = __float_as_uint(odd ? v03 : v02);
                a[mt][2] = __float_as_uint(odd ? v11 : v10);
                a[mt][3] = __float_as_uint(odd ? v13 : v12);
            }
            #pragma unroll
            for (int dj = 0; dj < 4; dj++) {
                uint32_t b[4];
                ldsm4(b, VT + (dj * 16 + br16) * AP + k8 * 8 + bc4);
                #pragma unroll
                for (int mt = 0; mt < 2; mt++) {
                    mma_tf32(oacc[mt][2 * dj + 0], a[mt], &b[0]);
                    mma_tf32(oacc[mt][2 * dj + 1], a[mt], &b[2]);
                }
            }
        }
    }

    // ---- epilogue ----
    #pragma unroll
    for (int mt = 0; mt < 2; mt++) {
        const float inv0 = 1.f / run_s[mt][0];
        const float inv1 = 1.f / run_s[mt][1];
        #pragma unroll
        for (int d8 = 0; d8 < 8; d8++) {
            const int dcol = d8 * 8 + 2 * t;
            {
                const int srow = qt * 128 + warp * 32 + mt * 16 + g;
                float2 v;
                v.x = tf32r(oacc[mt][d8][0] * inv0);
                v.y = tf32r(oacc[mt][d8][1] * inv0);
                *(float2*)&ctx[((size_t)bb * Sc + srow) * Ec + hh * Dc + dcol] = v;
            }
            {
                const int srow = qt * 128 + warp * 32 + mt * 16 + g + 8;
                float2 v;
                v.x = tf32r(oacc[mt][d8][2] * inv1);
                v.y = tf32r(oacc[mt][d8][3] * inv1);
                *(float2*)&ctx[((size_t)bb * Sc + srow) * Ec + hh * Dc + dcol] = v;
            }
        }
    }
}

// ---------------------------------------------------------------------------
extern "C" void kernel_launch(void* const* d_in, const int* in_sizes, int n_in,
                              void* d_out, int out_size)
{
    const float* x_q  = (const float*)d_in[0];
    const float* x_k  = (const float*)d_in[1];
    const float* x_v  = (const float*)d_in[2];
    const float* Wq   = (const float*)d_in[3];
    const float* bq   = (const float*)d_in[4];
    const float* Wk   = (const float*)d_in[5];
    const float* bk   = (const float*)d_in[6];
    const float* Wv   = (const float*)d_in[7];
    const float* bv   = (const float*)d_in[8];
    const float* Wo   = (const float*)d_in[9];
    const float* bo   = (const float*)d_in[10];
    const float* temp = (const float*)d_in[11];
    const float* cosT = (const float*)d_in[12];
    const float* sinT = (const float*)d_in[13];
    float* out = (float*)d_out;

    float *pQ, *pK, *pV, *pC, *cxq, *cxk, *cxv, *cwq, *cwk, *cwv, *cwo;
    cudaGetSymbolAddress((void**)&pQ, g_Q);
    cudaGetSymbolAddress((void**)&pK, g_K);
    cudaGetSymbolAddress((void**)&pV, g_V);
    cudaGetSymbolAddress((void**)&pC, g_ctx);
    cudaGetSymbolAddress((void**)&cxq, g_cxq);
    cudaGetSymbolAddress((void**)&cxk, g_cxk);
    cudaGetSymbolAddress((void**)&cxv, g_cxv);
    cudaGetSymbolAddress((void**)&cwq, g_cwq);
    cudaGetSymbolAddress((void**)&cwk, g_cwk);
    cudaGetSymbolAddress((void**)&cwv, g_cwv);
    cudaGetSymbolAddress((void**)&cwo, g_cwo);

    cudaFuncSetAttribute(gemm_qkv,
                         cudaFuncAttributeMaxDynamicSharedMemorySize, SMEM_GEMM);
    cudaFuncSetAttribute(gemm_out,
                         cudaFuncAttributeMaxDynamicSharedMemorySize, SMEM_GEMM);
    cudaFuncSetAttribute(attn_flash,
                         cudaFuncAttributeMaxDynamicSharedMemorySize, SMEM_FLASH);

    const int nx4 = Mrows * Ec / 4;   // 1M
    const int nw4 = Ec * Ec / 4;      // 256K

    cvt_all<<<dim3((nx4 + 255) / 256, 7), 256>>>(
        x_q, x_k, x_v, Wq, Wk, Wv, Wo,
        cxq, cxk, cxv, cwq, cwk, cwv, cwo, nx4, nw4);

    gemm_qkv<<<dim3(Ec / 128, Mrows / 128, 3), 256, SMEM_GEMM>>>(
        cxq, cxk, cxv, cwq, cwk, cwv, bq, bk, bv, pQ, pK, pV);

    rope_l2<<<dim3((Bc * Hc * Sc) / 8, 2), 256>>>(pQ, pK, cosT, sinT, temp);

    attn_flash<<<dim3(4, Bc * Hc), 128, SMEM_FLASH>>>(pQ, pK, pV, pC);

    gemm_out<<<dim3(Ec / 128, Mrows / 128), 256, SMEM_GEMM>>>(pC, cwo, bo, out);
}

// round 9
// speedup vs baseline: 1.0868x; 1.0117x over previous
#include <cuda_runtime.h>
#include <cuda_bf16.h>
#include <math.h>
#include <cstdint>

// Problem constants
constexpr int Bc = 8;
constexpr int Sc = 512;
constexpr int Ec = 1024;
constexpr int Hc = 16;
constexpr int Dc = 64;
constexpr int Mrows = Bc * Sc;   // 4096

// Scratch (static device arrays: allocation-free)
__device__ float g_Q[(size_t)Mrows * Ec];
__device__ float g_K[(size_t)Mrows * Ec];
__device__ float g_V[(size_t)Mrows * Ec];
__device__ float g_ctx[(size_t)Mrows * Ec];
__device__ float g_cxq[(size_t)Mrows * Ec];
__device__ float g_cxk[(size_t)Mrows * Ec];
__device__ float g_cxv[(size_t)Mrows * Ec];
__device__ float g_cwq[(size_t)Ec * Ec];
__device__ float g_cwk[(size_t)Ec * Ec];
__device__ float g_cwv[(size_t)Ec * Ec];
__device__ float g_cwo[(size_t)Ec * Ec];

// ---------------------------------------------------------------------------
// helpers
// ---------------------------------------------------------------------------
__device__ __forceinline__ uint32_t s2u(const void* p) {
    uint32_t a;
    asm("{ .reg .u64 t; cvta.to.shared.u64 t, %1; cvt.u32.u64 %0, t; }"
        : "=r"(a) : "l"(p));
    return a;
}

__device__ __forceinline__ void cp_async16(uint32_t saddr, const void* gaddr) {
    asm volatile("cp.async.cg.shared.global [%0], [%1], 16;" :: "r"(saddr), "l"(gaddr));
}
#define CP_COMMIT() asm volatile("cp.async.commit_group;" ::: "memory")
#define CP_WAIT(n)  asm volatile("cp.async.wait_group %0;" :: "n"(n) : "memory")

__device__ __forceinline__ float tf32r(float f) {
    uint32_t u;
    asm("cvt.rna.tf32.f32 %0, %1;" : "=r"(u) : "f"(f));
    return __uint_as_float(u);
}

__device__ __forceinline__ void mma_tf32(float* d, const uint32_t* a, const uint32_t* b) {
    asm volatile(
        "mma.sync.aligned.m16n8k8.row.col.f32.tf32.tf32.f32 "
        "{%0,%1,%2,%3}, {%4,%5,%6,%7}, {%8,%9}, {%0,%1,%2,%3};"
        : "+f"(d[0]), "+f"(d[1]), "+f"(d[2]), "+f"(d[3])
        : "r"(a[0]), "r"(a[1]), "r"(a[2]), "r"(a[3]), "r"(b[0]), "r"(b[1]));
}

__device__ __forceinline__ void ldsm4(uint32_t* r, const void* smem_ptr) {
    uint32_t a = s2u(smem_ptr);
    asm volatile("ldmatrix.sync.aligned.m8n8.x4.shared.b16 {%0,%1,%2,%3}, [%4];"
                 : "=r"(r[0]), "=r"(r[1]), "=r"(r[2]), "=r"(r[3]) : "r"(a));
}

// ---------------------------------------------------------------------------
// fused fp32 -> tf32 pre-pass for all 7 tensors (grid.y selects)
// ---------------------------------------------------------------------------
__global__ void cvt_all(const float* i0, const float* i1, const float* i2,
                        const float* i3, const float* i4, const float* i5,
                        const float* i6,
                        float* o0, float* o1, float* o2, float* o3,
                        float* o4, float* o5, float* o6,
                        int nx4, int nw4) {
    const int y = blockIdx.y;
    const float* in;
    float* out;
    int n4;
    switch (y) {
        case 0: in = i0; out = o0; n4 = nx4; break;
        case 1: in = i1; out = o1; n4 = nx4; break;
        case 2: in = i2; out = o2; n4 = nx4; break;
        case 3: in = i3; out = o3; n4 = nw4; break;
        case 4: in = i4; out = o4; n4 = nw4; break;
        case 5: in = i5; out = o5; n4 = nw4; break;
        default: in = i6; out = o6; n4 = nw4; break;
    }
    int i = blockIdx.x * blockDim.x + threadIdx.x;
    if (i >= n4) return;
    float4 v = ((const float4*)in)[i];
    v.x = tf32r(v.x); v.y = tf32r(v.y); v.z = tf32r(v.z); v.w = tf32r(v.w);
    ((float4*)out)[i] = v;
}

// ---------------------------------------------------------------------------
// tf32 HMMA GEMM: CTA tile 128x256, warp tile 64x64 (2x4 warps), BK=32,
// 2-stage cp.async double buffer. Inputs pre-rounded tf32.
// ---------------------------------------------------------------------------
constexpr int BK = 32;
constexpr int PITCH = 36;
constexpr int NCH = Ec / BK;                      // 32
constexpr int A_TILE_F = 128 * PITCH;             // 4608
constexpr int B_TILE_F = 256 * PITCH;             // 9216
constexpr int STAGE_F = A_TILE_F + B_TILE_F;      // 13824
constexpr int SMEM_GEMM = 2 * STAGE_F * 4;        // 110592 B

__device__ __forceinline__
void gemm_body(const float* __restrict__ A, const float* __restrict__ W,
               const float* __restrict__ bias, float* __restrict__ out,
               int scatter, int round_out, float* sm)
{
    const int tid = threadIdx.x;
    const int lane = tid & 31;
    const int wid = tid >> 5;
    const int warp_m = wid >> 2;          // 0..1  (64 m-rows each)
    const int warp_n = wid & 3;           // 0..3  (64 n-cols each)
    const int g = lane >> 2;
    const int t = lane & 3;
    const int m0 = blockIdx.y * 128;
    const int n0 = blockIdx.x * 256;

    const int aRow = warp_m * 64 + ((lane >> 3) & 1) * 8 + (lane & 7);
    const int aCol = (lane >> 4) * 4;
    const int bRow = warp_n * 64 + (lane >> 4) * 8 + (lane & 7);
    const int bCol = ((lane >> 3) & 1) * 4;

    float d[4][8][4];
    #pragma unroll
    for (int i = 0; i < 4; i++)
        #pragma unroll
        for (int j = 0; j < 8; j++)
            #pragma unroll
            for (int k = 0; k < 4; k++) d[i][j][k] = 0.f;

    const float* gA0 = A + (size_t)m0 * Ec;
    const float* gW0 = W + (size_t)n0 * Ec;

    auto load_stage = [&](int c) {
        float* As = sm + (c & 1) * STAGE_F;
        float* Bs = As + A_TILE_F;
        const float* gA = gA0 + c * BK;
        const float* gW = gW0 + c * BK;
        #pragma unroll
        for (int i = 0; i < 4; i++) {      // A: 128 rows x 8 segs = 1024
            const int idx = tid + i * 256;
            const int row = idx >> 3, seg = idx & 7;
            cp_async16(s2u(As + row * PITCH + seg * 4),
                       gA + (size_t)row * Ec + seg * 4);
        }
        #pragma unroll
        for (int i = 0; i < 8; i++) {      // B: 256 rows x 8 segs = 2048
            const int idx = tid + i * 256;
            const int row = idx >> 3, seg = idx & 7;
            cp_async16(s2u(Bs + row * PITCH + seg * 4),
                       gW + (size_t)row * Ec + seg * 4);
        }
    };

    load_stage(0); CP_COMMIT();

    for (int c = 0; c < NCH; c++) {
        CP_WAIT(0);
        __syncthreads();   // chunk c visible; all warps done with chunk c-1

        if (c + 1 < NCH) { load_stage(c + 1); CP_COMMIT(); }

        const float* As = sm + (c & 1) * STAGE_F;
        const float* Bs = As + A_TILE_F;

        #pragma unroll
        for (int ks = 0; ks < 4; ks++) {
            uint32_t a[4][4], b[4][4];
            #pragma unroll
            for (int mt = 0; mt < 4; mt++)
                ldsm4(a[mt], As + (aRow + mt * 16) * PITCH + ks * 8 + aCol);
            #pragma unroll
            for (int j = 0; j < 4; j++)
                ldsm4(b[j], Bs + (bRow + j * 16) * PITCH + ks * 8 + bCol);
            #pragma unroll
            for (int mt = 0; mt < 4; mt++)
                #pragma unroll
                for (int j = 0; j < 4; j++) {
                    mma_tf32(d[mt][2 * j + 0], a[mt], &b[j][0]);
                    mma_tf32(d[mt][2 * j + 1], a[mt], &b[j][2]);
                }
        }
    }

    #pragma unroll
    for (int mt = 0; mt < 4; mt++) {
        #pragma unroll
        for (int nt = 0; nt < 8; nt++) {
            const int n = n0 + warp_n * 64 + nt * 8 + 2 * t;
            const float b0 = bias[n], b1 = bias[n + 1];
            #pragma unroll
            for (int half = 0; half < 2; half++) {
                const int m = m0 + warp_m * 64 + mt * 16 + g + half * 8;
                float2 v;
                v.x = d[mt][nt][half * 2 + 0] + b0;
                v.y = d[mt][nt][half * 2 + 1] + b1;
                if (round_out) { v.x = tf32r(v.x); v.y = tf32r(v.y); }
                if (scatter == 0) {
                    const int bb = m >> 9, ss = m & (Sc - 1);
                    const int hh = n >> 6, dd = n & (Dc - 1);
                    *(float2*)&out[((((size_t)bb * Hc + hh) * Sc + ss) << 6) + dd] = v;
                } else {
                    *(float2*)&out[(size_t)m * Ec + n] = v;
                }
            }
        }
    }
}

__global__ __launch_bounds__(256, 1)
void gemm_qkv(const float* A0, const float* A1, const float* A2,
              const float* W0, const float* W1, const float* W2,
              const float* b0, const float* b1, const float* b2,
              float* o0, float* o1, float* o2)
{
    extern __shared__ float sm[];
    const int z = blockIdx.z;
    const float* A = z == 0 ? A0 : z == 1 ? A1 : A2;
    const float* W = z == 0 ? W0 : z == 1 ? W1 : W2;
    const float* bi = z == 0 ? b0 : z == 1 ? b1 : b2;
    float* out = z == 0 ? o0 : z == 1 ? o1 : o2;
    gemm_body(A, W, bi, out, 0, z == 2 ? 1 : 0, sm);
}

__global__ __launch_bounds__(256, 1)
void gemm_out(const float* __restrict__ A, const float* __restrict__ W,
              const float* __restrict__ bias, float* __restrict__ out)
{
    extern __shared__ float sm[];
    gemm_body(A, W, bias, out, 1, 0, sm);
}

// ---------------------------------------------------------------------------
// RoPE + L2 norm; Q scaled by temperature. tf32-rounded output.
// ---------------------------------------------------------------------------
__global__ void rope_l2(float* __restrict__ TQ, float* __restrict__ TK,
                        const float* __restrict__ cosT,
                        const float* __restrict__ sinT,
                        const float* __restrict__ tempPtr)
{
    float* T = blockIdx.y ? TK : TQ;
    const float scale = blockIdx.y ? 1.0f : *tempPtr;
    const int row = blockIdx.x * 8 + (threadIdx.x >> 5);
    const int lane = threadIdx.x & 31;
    const int s = row & (Sc - 1);

    float2* p = (float2*)(T + (size_t)row * Dc);
    float2 v = p[lane];
    const float c = cosT[s * 32 + lane];
    const float sn = sinT[s * 32 + lane];
    const float r0 = v.x * c - v.y * sn;
    const float r1 = v.x * sn + v.y * c;

    float ss = r0 * r0 + r1 * r1;
    #pragma unroll
    for (int o = 16; o; o >>= 1) ss += __shfl_xor_sync(0xffffffffu, ss, o);
    const float inv = scale / fmaxf(sqrtf(ss), 1e-12f);

    p[lane] = make_float2(tf32r(r0 * inv), tf32r(r1 * inv));
}

// ---------------------------------------------------------------------------
// Flash attention v3: q-tile 128, warp owns 32 q-rows. FIXED-MAX softmax:
// q,k are L2-normalized so |score| <= |temp| (Cauchy-Schwarz); use M=|temp|
// as the softmax max -> no running max, no rescale, per-lane sums reduced once.
// smem: QT[128][68] | Kb0[64][68] | Kb1 | Vl[64][68] | VT[64][68] = 104448 B
// ---------------------------------------------------------------------------
constexpr int AP = 68;
constexpr int QT_F = 128 * AP;
constexpr int KV_F = 64 * AP;
constexpr int SMEM_FLASH = (QT_F + 4 * KV_F) * 4;  // 104448 B

__global__ __launch_bounds__(128, 2)
void attn_flash(const float* __restrict__ Q,
                const float* __restrict__ K,
                const float* __restrict__ V,
                float* __restrict__ ctx,
                const float* __restrict__ tempPtr)
{
    extern __shared__ float smf[];
    float* QT  = smf;
    float* Kb0 = smf + QT_F;
    float* Kb1 = Kb0 + KV_F;
    float* Vl  = Kb1 + KV_F;
    float* VT  = Vl + KV_F;

    const int tid = threadIdx.x;
    const int lane = tid & 31;
    const int warp = tid >> 5;
    const int g = lane >> 2;
    const int t = lane & 3;
    const int qt = blockIdx.x;
    const int bh = blockIdx.y;
    const int bb = bh >> 4;
    const int hh = bh & 15;
    const size_t head_off = (size_t)bh * Sc * Dc;
    const float M = fabsf(*tempPtr);      // provable score bound

    const int lr8 = ((lane >> 3) & 1) * 8 + (lane & 7);
    const int lc4 = (lane >> 4) * 4;
    const int br16 = (lane >> 4) * 8 + (lane & 7);
    const int bc4 = ((lane >> 3) & 1) * 4;

    const int vd4 = tid >> 3;
    const int vr0 = tid & 7;

    // ---- load Q tile [128][64] ----
    {
        const float4* src = (const float4*)(Q + head_off + (size_t)qt * 128 * Dc);
        for (int i = tid; i < 2048; i += 128) {
            const int r = i >> 4, c4 = i & 15;
            *(float4*)&QT[r * AP + c4 * 4] = src[i];
        }
    }

    // ---- prefetch K/V chunk 0 ----
    {
        const float* gK = K + head_off;
        const float* gV = V + head_off;
        #pragma unroll
        for (int i = 0; i < 8; i++) {
            const int idx = tid + i * 128;
            const int r = idx >> 4, seg = idx & 15;
            cp_async16(s2u(Kb0 + r * AP + seg * 4), gK + (size_t)r * Dc + seg * 4);
            cp_async16(s2u(Vl + r * AP + seg * 4), gV + (size_t)r * Dc + seg * 4);
        }
        CP_COMMIT();
    }

    // per-lane partial sums per m-tile (rows g / g+8)
    float run_s[2][2] = {{0.f, 0.f}, {0.f, 0.f}};
    float oacc[2][8][4];
    #pragma unroll
    for (int mt = 0; mt < 2; mt++)
        #pragma unroll
        for (int j = 0; j < 8; j++)
            #pragma unroll
            for (int k = 0; k < 4; k++) oacc[mt][j][k] = 0.f;

    const uint32_t fullm = 0xffffffffu;
    const int src0 = (lane & ~3) | (t >> 1);
    const int src1 = src0 + 2;
    const bool odd = (t & 1) != 0;

    for (int kt = 0; kt < 8; kt++) {
        float* Kc = (kt & 1) ? Kb1 : Kb0;
        float* Kn = (kt & 1) ? Kb0 : Kb1;

        CP_WAIT(0);
        __syncthreads();

        // ---- transpose Vl[key][d] -> VT[d][key] ----
        #pragma unroll
        for (int p = 0; p < 8; p++) {
            const int key = vr0 + 8 * p;
            float4 v = *(const float4*)&Vl[key * AP + vd4 * 4];
            VT[(vd4 * 4 + 0) * AP + key] = v.x;
            VT[(vd4 * 4 + 1) * AP + key] = v.y;
            VT[(vd4 * 4 + 2) * AP + key] = v.z;
            VT[(vd4 * 4 + 3) * AP + key] = v.w;
        }
        __syncthreads();

        if (kt < 7) {
            const float* gK = K + head_off + (size_t)(kt + 1) * 64 * Dc;
            const float* gV = V + head_off + (size_t)(kt + 1) * 64 * Dc;
            #pragma unroll
            for (int i = 0; i < 8; i++) {
                const int idx = tid + i * 128;
                const int r = idx >> 4, seg = idx & 15;
                cp_async16(s2u(Kn + r * AP + seg * 4), gK + (size_t)r * Dc + seg * 4);
                cp_async16(s2u(Vl + r * AP + seg * 4), gV + (size_t)r * Dc + seg * 4);
            }
            CP_COMMIT();
        }

        // ---- QK^T ----
        float s[2][8][4];
        #pragma unroll
        for (int mt = 0; mt < 2; mt++)
            #pragma unroll
            for (int j = 0; j < 8; j++)
                #pragma unroll
                for (int k = 0; k < 4; k++) s[mt][j][k] = 0.f;

        #pragma unroll
        for (int ks = 0; ks < 8; ks++) {
            uint32_t a[2][4], b[4][4];
            #pragma unroll
            for (int mt = 0; mt < 2; mt++)
                ldsm4(a[mt], QT + (warp * 32 + mt * 16 + lr8) * AP + ks * 8 + lc4);
            #pragma unroll
            for (int jj = 0; jj < 4; jj++)
                ldsm4(b[jj], Kc + (jj * 16 + br16) * AP + ks * 8 + bc4);
            #pragma unroll
            for (int mt = 0; mt < 2; mt++)
                #pragma unroll
                for (int jj = 0; jj < 4; jj++) {
                    mma_tf32(s[mt][2 * jj + 0], a[mt], &b[jj][0]);
                    mma_tf32(s[mt][2 * jj + 1], a[mt], &b[jj][2]);
                }
        }

        // ---- fixed-max softmax: p = exp(s - M), per-lane sum ----
        #pragma unroll
        for (int mt = 0; mt < 2; mt++) {
            #pragma unroll
            for (int j = 0; j < 8; j++) {
                float p0 = __expf(s[mt][j][0] - M);
                float p1 = __expf(s[mt][j][1] - M);
                float p2 = __expf(s[mt][j][2] - M);
                float p3 = __expf(s[mt][j][3] - M);
                run_s[mt][0] += p0 + p1;
                run_s[mt][1] += p2 + p3;
                s[mt][j][0] = tf32r(p0); s[mt][j][1] = tf32r(p1);
                s[mt][j][2] = tf32r(p2); s[mt][j][3] = tf32r(p3);
            }
        }

        // ---- PV: shuffle-permute probs; V^T frags shared across m-tiles ----
        #pragma unroll
        for (int k8 = 0; k8 < 8; k8++) {
            uint32_t a[2][4];
            #pragma unroll
            for (int mt = 0; mt < 2; mt++) {
                float v00 = __shfl_sync(fullm, s[mt][k8][0], src0);
                float v01 = __shfl_sync(fullm, s[mt][k8][1], src0);
                float v02 = __shfl_sync(fullm, s[mt][k8][2], src0);
                float v03 = __shfl_sync(fullm, s[mt][k8][3], src0);
                float v10 = __shfl_sync(fullm, s[mt][k8][0], src1);
                float v11 = __shfl_sync(fullm, s[mt][k8][1], src1);
                float v12 = __shfl_sync(fullm, s[mt][k8][2], src1);
                float v13 = __shfl_sync(fullm, s[mt][k8][3], src1);
                a[mt][0] = __float_as_uint(odd ? v01 : v00);
                a[mt][1] = __float_as_uint(odd ? v03 : v02);
                a[mt][2] = __float_as_uint(odd ? v11 : v10);
                a[mt][3] = __float_as_uint(odd ? v13 : v12);
            }
            #pragma unroll
            for (int dj = 0; dj < 4; dj++) {
                uint32_t b[4];
                ldsm4(b, VT + (dj * 16 + br16) * AP + k8 * 8 + bc4);
                #pragma unroll
                for (int mt = 0; mt < 2; mt++) {
                    mma_tf32(oacc[mt][2 * dj + 0], a[mt], &b[0]);
                    mma_tf32(oacc[mt][2 * dj + 1], a[mt], &b[2]);
                }
            }
        }
    }

    // ---- reduce row sums across quad (lanes sharing g) ----
    #pragma unroll
    for (int mt = 0; mt < 2; mt++)
        #pragma unroll
        for (int h = 0; h < 2; h++) {
            run_s[mt][h] += __shfl_xor_sync(fullm, run_s[mt][h], 1);
            run_s[mt][h] += __shfl_xor_sync(fullm, run_s[mt][h], 2);
        }

    // ---- epilogue ----
    #pragma unroll
    for (int mt = 0; mt < 2; mt++) {
        const float inv0 = 1.f / run_s[mt][0];
        const float inv1 = 1.f / run_s[mt][1];
        #pragma unroll
        for (int d8 = 0; d8 < 8; d8++) {
            const int dcol = d8 * 8 + 2 * t;
            {
                const int srow = qt * 128 + warp * 32 + mt * 16 + g;
                float2 v;
                v.x = tf32r(oacc[mt][d8][0] * inv0);
                v.y = tf32r(oacc[mt][d8][1] * inv0);
                *(float2*)&ctx[((size_t)bb * Sc + srow) * Ec + hh * Dc + dcol] = v;
            }
            {
                const int srow = qt * 128 + warp * 32 + mt * 16 + g + 8;
                float2 v;
                v.x = tf32r(oacc[mt][d8][2] * inv1);
                v.y = tf32r(oacc[mt][d8][3] * inv1);
                *(float2*)&ctx[((size_t)bb * Sc + srow) * Ec + hh * Dc + dcol] = v;
            }
        }
    }
}

// ---------------------------------------------------------------------------
extern "C" void kernel_launch(void* const* d_in, const int* in_sizes, int n_in,
                              void* d_out, int out_size)
{
    const float* x_q  = (const float*)d_in[0];
    const float* x_k  = (const float*)d_in[1];
    const float* x_v  = (const float*)d_in[2];
    const float* Wq   = (const float*)d_in[3];
    const float* bq   = (const float*)d_in[4];
    const float* Wk   = (const float*)d_in[5];
    const float* bk   = (const float*)d_in[6];
    const float* Wv   = (const float*)d_in[7];
    const float* bv   = (const float*)d_in[8];
    const float* Wo   = (const float*)d_in[9];
    const float* bo   = (const float*)d_in[10];
    const float* temp = (const float*)d_in[11];
    const float* cosT = (const float*)d_in[12];
    const float* sinT = (const float*)d_in[13];
    float* out = (float*)d_out;

    float *pQ, *pK, *pV, *pC, *cxq, *cxk, *cxv, *cwq, *cwk, *cwv, *cwo;
    cudaGetSymbolAddress((void**)&pQ, g_Q);
    cudaGetSymbolAddress((void**)&pK, g_K);
    cudaGetSymbolAddress((void**)&pV, g_V);
    cudaGetSymbolAddress((void**)&pC, g_ctx);
    cudaGetSymbolAddress((void**)&cxq, g_cxq);
    cudaGetSymbolAddress((void**)&cxk, g_cxk);
    cudaGetSymbolAddress((void**)&cxv, g_cxv);
    cudaGetSymbolAddress((void**)&cwq, g_cwq);
    cudaGetSymbolAddress((void**)&cwk, g_cwk);
    cudaGetSymbolAddress((void**)&cwv, g_cwv);
    cudaGetSymbolAddress((void**)&cwo, g_cwo);

    cudaFuncSetAttribute(gemm_qkv,
                         cudaFuncAttributeMaxDynamicSharedMemorySize, SMEM_GEMM);
    cudaFuncSetAttribute(gemm_out,
                         cudaFuncAttributeMaxDynamicSharedMemorySize, SMEM_GEMM);
    cudaFuncSetAttribute(attn_flash,
                         cudaFuncAttributeMaxDynamicSharedMemorySize, SMEM_FLASH);

    const int nx4 = Mrows * Ec / 4;   // 1M
    const int nw4 = Ec * Ec / 4;      // 256K

    cvt_all<<<dim3((nx4 + 255) / 256, 7), 256>>>(
        x_q, x_k, x_v, Wq, Wk, Wv, Wo,
        cxq, cxk, cxv, cwq, cwk, cwv, cwo, nx4, nw4);

    gemm_qkv<<<dim3(Ec / 256, Mrows / 128, 3), 256, SMEM_GEMM>>>(
        cxq, cxk, cxv, cwq, cwk, cwv, bq, bk, bv, pQ, pK, pV);

    rope_l2<<<dim3((Bc * Hc * Sc) / 8, 2), 256>>>(pQ, pK, cosT, sinT, temp);

    attn_flash<<<dim3(4, Bc * Hc), 128, SMEM_FLASH>>>(pQ, pK, pV, pC, temp);

    gemm_out<<<dim3(Ec / 256, Mrows / 128), 256, SMEM_GEMM>>>(pC, cwo, bo, out);
}

// round 10
// speedup vs baseline: 1.1008x; 1.0129x over previous
#include <cuda_runtime.h>
#include <cuda_bf16.h>
#include <math.h>
#include <cstdint>

// Problem constants
constexpr int Bc = 8;
constexpr int Sc = 512;
constexpr int Ec = 1024;
constexpr int Hc = 16;
constexpr int Dc = 64;
constexpr int Mrows = Bc * Sc;   // 4096

// Scratch (static device arrays: allocation-free)
__device__ float g_Q[(size_t)Mrows * Ec];
__device__ float g_K[(size_t)Mrows * Ec];
__device__ float g_V[(size_t)Mrows * Ec];
__device__ float g_ctx[(size_t)Mrows * Ec];
__device__ float g_cxq[(size_t)Mrows * Ec];
__device__ float g_cxk[(size_t)Mrows * Ec];
__device__ float g_cxv[(size_t)Mrows * Ec];
__device__ float g_cwq[(size_t)Ec * Ec];
__device__ float g_cwk[(size_t)Ec * Ec];
__device__ float g_cwv[(size_t)Ec * Ec];
__device__ float g_cwo[(size_t)Ec * Ec];

// ---------------------------------------------------------------------------
// helpers
// ---------------------------------------------------------------------------
__device__ __forceinline__ uint32_t s2u(const void* p) {
    uint32_t a;
    asm("{ .reg .u64 t; cvta.to.shared.u64 t, %1; cvt.u32.u64 %0, t; }"
        : "=r"(a) : "l"(p));
    return a;
}

__device__ __forceinline__ void cp_async16(uint32_t saddr, const void* gaddr) {
    asm volatile("cp.async.cg.shared.global [%0], [%1], 16;" :: "r"(saddr), "l"(gaddr));
}
#define CP_COMMIT() asm volatile("cp.async.commit_group;" ::: "memory")
#define CP_WAIT(n)  asm volatile("cp.async.wait_group %0;" :: "n"(n) : "memory")

__device__ __forceinline__ float tf32r(float f) {
    uint32_t u;
    asm("cvt.rna.tf32.f32 %0, %1;" : "=r"(u) : "f"(f));
    return __uint_as_float(u);
}

__device__ __forceinline__ void mma_tf32(float* d, const uint32_t* a, const uint32_t* b) {
    asm volatile(
        "mma.sync.aligned.m16n8k8.row.col.f32.tf32.tf32.f32 "
        "{%0,%1,%2,%3}, {%4,%5,%6,%7}, {%8,%9}, {%0,%1,%2,%3};"
        : "+f"(d[0]), "+f"(d[1]), "+f"(d[2]), "+f"(d[3])
        : "r"(a[0]), "r"(a[1]), "r"(a[2]), "r"(a[3]), "r"(b[0]), "r"(b[1]));
}

__device__ __forceinline__ void ldsm4(uint32_t* r, const void* smem_ptr) {
    uint32_t a = s2u(smem_ptr);
    asm volatile("ldmatrix.sync.aligned.m8n8.x4.shared.b16 {%0,%1,%2,%3}, [%4];"
                 : "=r"(r[0]), "=r"(r[1]), "=r"(r[2]), "=r"(r[3]) : "r"(a));
}

// ---------------------------------------------------------------------------
// fused fp32 -> tf32 pre-pass for all 7 tensors (grid.y selects)
// ---------------------------------------------------------------------------
__global__ void cvt_all(const float* i0, const float* i1, const float* i2,
                        const float* i3, const float* i4, const float* i5,
                        const float* i6,
                        float* o0, float* o1, float* o2, float* o3,
                        float* o4, float* o5, float* o6,
                        int nx4, int nw4) {
    const int y = blockIdx.y;
    const float* in;
    float* out;
    int n4;
    switch (y) {
        case 0: in = i0; out = o0; n4 = nx4; break;
        case 1: in = i1; out = o1; n4 = nx4; break;
        case 2: in = i2; out = o2; n4 = nx4; break;
        case 3: in = i3; out = o3; n4 = nw4; break;
        case 4: in = i4; out = o4; n4 = nw4; break;
        case 5: in = i5; out = o5; n4 = nw4; break;
        default: in = i6; out = o6; n4 = nw4; break;
    }
    int i = blockIdx.x * blockDim.x + threadIdx.x;
    if (i >= n4) return;
    float4 v = ((const float4*)in)[i];
    v.x = tf32r(v.x); v.y = tf32r(v.y); v.z = tf32r(v.z); v.w = tf32r(v.w);
    ((float4*)out)[i] = v;
}

// ---------------------------------------------------------------------------
// tf32 HMMA GEMM: CTA 128x128, 128 threads (4 warps, 2x2), warp tile 64x64,
// BK=32, 3-stage cp.async, 2 CTAs/SM. High AI (32 ldsm / 128 HMMA per chunk).
// mode 0: rope+l2norm+temp scatter (Q)   mode 1: rope+l2norm scatter (K)
// mode 2: bias+round scatter (V)         mode 3: plain row-major (out)
// ---------------------------------------------------------------------------
constexpr int BK = 32;
constexpr int PITCH = 36;
constexpr int STAGES = 3;
constexpr int TILE_F = 128 * PITCH;
constexpr int STAGE_F = 2 * TILE_F;
constexpr int NCH = Ec / BK;
constexpr int SMEM_GEMM = STAGES * STAGE_F * 4;   // 110592 B

__device__ __forceinline__
void gemm_body(const float* __restrict__ A, const float* __restrict__ W,
               const float* __restrict__ bias, float* __restrict__ out,
               int mode, const float* __restrict__ cosT,
               const float* __restrict__ sinT, float scale, float* sm)
{
    const int tid = threadIdx.x;
    const int lane = tid & 31;
    const int wid = tid >> 5;             // 0..3
    const int warp_m = wid >> 1;          // 0..1
    const int warp_n = wid & 1;           // 0..1
    const int g = lane >> 2;
    const int t = lane & 3;
    const int m0 = blockIdx.y * 128;
    const int n0 = blockIdx.x * 128;

    const int aRow = warp_m * 64 + ((lane >> 3) & 1) * 8 + (lane & 7);
    const int aCol = (lane >> 4) * 4;
    const int bRow = warp_n * 64 + (lane >> 4) * 8 + (lane & 7);
    const int bCol = ((lane >> 3) & 1) * 4;

    float d[4][8][4];
    #pragma unroll
    for (int i = 0; i < 4; i++)
        #pragma unroll
        for (int j = 0; j < 8; j++)
            #pragma unroll
            for (int k = 0; k < 4; k++) d[i][j][k] = 0.f;

    const float* gA0 = A + (size_t)m0 * Ec;
    const float* gW0 = W + (size_t)n0 * Ec;

    auto load_stage = [&](int c) {
        float* As = sm + (c % STAGES) * STAGE_F;
        float* Bs = As + TILE_F;
        const float* gA = gA0 + c * BK;
        const float* gW = gW0 + c * BK;
        #pragma unroll
        for (int i = 0; i < 8; i++) {
            const int idx = tid + i * 128;         // 0..1023
            const int row = idx >> 3, seg = idx & 7;
            cp_async16(s2u(As + row * PITCH + seg * 4),
                       gA + (size_t)row * Ec + seg * 4);
            cp_async16(s2u(Bs + row * PITCH + seg * 4),
                       gW + (size_t)row * Ec + seg * 4);
        }
    };

    load_stage(0); CP_COMMIT();
    load_stage(1); CP_COMMIT();

    for (int c = 0; c < NCH; c++) {
        if (c + 1 < NCH) { CP_WAIT(1); } else { CP_WAIT(0); }
        __syncthreads();

        if (c + 2 < NCH) { load_stage(c + 2); CP_COMMIT(); }

        const float* As = sm + (c % STAGES) * STAGE_F;
        const float* Bs = As + TILE_F;

        #pragma unroll
        for (int ks = 0; ks < 4; ks++) {
            uint32_t a[4][4], b[4][4];
            #pragma unroll
            for (int mt = 0; mt < 4; mt++)
                ldsm4(a[mt], As + (aRow + mt * 16) * PITCH + ks * 8 + aCol);
            #pragma unroll
            for (int j = 0; j < 4; j++)
                ldsm4(b[j], Bs + (bRow + j * 16) * PITCH + ks * 8 + bCol);
            #pragma unroll
            for (int mt = 0; mt < 4; mt++)
                #pragma unroll
                for (int j = 0; j < 4; j++) {
                    mma_tf32(d[mt][2 * j + 0], a[mt], &b[j][0]);
                    mma_tf32(d[mt][2 * j + 1], a[mt], &b[j][2]);
                }
        }
    }

    const uint32_t fullm = 0xffffffffu;

    if (mode <= 1) {
        // -------- fused bias + RoPE + L2 norm + (temp) + round + scatter ----
        // warp covers 64 consecutive n-cols = one full head
        #pragma unroll
        for (int mt = 0; mt < 4; mt++) {
            const int m_g = m0 + warp_m * 64 + mt * 16 + g;
            const int s0 = m_g & (Sc - 1);
            const int s1 = (m_g + 8) & (Sc - 1);
            float2 r0v[8], r1v[8];
            float ss0 = 0.f, ss1 = 0.f;
            #pragma unroll
            for (int nt = 0; nt < 8; nt++) {
                const int ncol = n0 + warp_n * 64 + (nt >> 1) * 16 + (nt & 1) * 8 + 2 * t;
                const int j = (ncol & 63) >> 1;
                const float b0 = bias[ncol], b1 = bias[ncol + 1];
                const float c0 = cosT[s0 * 32 + j], sn0 = sinT[s0 * 32 + j];
                const float c1 = cosT[s1 * 32 + j], sn1 = sinT[s1 * 32 + j];
                {
                    const float x = d[mt][nt][0] + b0;
                    const float y = d[mt][nt][1] + b1;
                    const float rx = x * c0 - y * sn0;
                    const float ry = x * sn0 + y * c0;
                    ss0 += rx * rx + ry * ry;
                    r0v[nt] = make_float2(rx, ry);
                }
                {
                    const float x = d[mt][nt][2] + b0;
                    const float y = d[mt][nt][3] + b1;
                    const float rx = x * c1 - y * sn1;
                    const float ry = x * sn1 + y * c1;
                    ss1 += rx * rx + ry * ry;
                    r1v[nt] = make_float2(rx, ry);
                }
            }
            // reduce across the 4 lanes of the quad (same g, t=0..3)
            ss0 += __shfl_xor_sync(fullm, ss0, 1);
            ss0 += __shfl_xor_sync(fullm, ss0, 2);
            ss1 += __shfl_xor_sync(fullm, ss1, 1);
            ss1 += __shfl_xor_sync(fullm, ss1, 2);
            const float inv0 = scale / fmaxf(sqrtf(ss0), 1e-12f);
            const float inv1 = scale / fmaxf(sqrtf(ss1), 1e-12f);

            #pragma unroll
            for (int nt = 0; nt < 8; nt++) {
                const int ncol = n0 + warp_n * 64 + (nt >> 1) * 16 + (nt & 1) * 8 + 2 * t;
                const int hh = ncol >> 6, dd = ncol & (Dc - 1);
                {
                    const int bb = m_g >> 9;
                    float2 v = make_float2(tf32r(r0v[nt].x * inv0),
                                           tf32r(r0v[nt].y * inv0));
                    *(float2*)&out[((((size_t)bb * Hc + hh) * Sc + s0) << 6) + dd] = v;
                }
                {
                    const int bb = (m_g + 8) >> 9;
                    float2 v = make_float2(tf32r(r1v[nt].x * inv1),
                                           tf32r(r1v[nt].y * inv1));
                    *(float2*)&out[((((size_t)bb * Hc + hh) * Sc + s1) << 6) + dd] = v;
                }
            }
        }
    } else {
        // -------- plain epilogues (V scatter+round, or out plain) ----------
        #pragma unroll
        for (int mt = 0; mt < 4; mt++) {
            #pragma unroll
            for (int nt = 0; nt < 8; nt++) {
                const int n = n0 + warp_n * 64 + (nt >> 1) * 16 + (nt & 1) * 8 + 2 * t;
                const float b0 = bias[n], b1 = bias[n + 1];
                #pragma unroll
                for (int half = 0; half < 2; half++) {
                    const int m = m0 + warp_m * 64 + mt * 16 + g + half * 8;
                    float2 v;
                    v.x = d[mt][nt][half * 2 + 0] + b0;
                    v.y = d[mt][nt][half * 2 + 1] + b1;
                    if (mode == 2) {
                        v.x = tf32r(v.x); v.y = tf32r(v.y);
                        const int bb = m >> 9, ss = m & (Sc - 1);
                        const int hh = n >> 6, dd = n & (Dc - 1);
                        *(float2*)&out[((((size_t)bb * Hc + hh) * Sc + ss) << 6) + dd] = v;
                    } else {
                        *(float2*)&out[(size_t)m * Ec + n] = v;
                    }
                }
            }
        }
    }
}

__global__ __launch_bounds__(128, 2)
void gemm_qkv(const float* A0, const float* A1, const float* A2,
              const float* W0, const float* W1, const float* W2,
              const float* b0, const float* b1, const float* b2,
              float* o0, float* o1, float* o2,
              const float* cosT, const float* sinT, const float* tempPtr)
{
    extern __shared__ float sm[];
    const int z = blockIdx.z;
    const float* A = z == 0 ? A0 : z == 1 ? A1 : A2;
    const float* W = z == 0 ? W0 : z == 1 ? W1 : W2;
    const float* bi = z == 0 ? b0 : z == 1 ? b1 : b2;
    float* out = z == 0 ? o0 : z == 1 ? o1 : o2;
    const float scale = (z == 0) ? *tempPtr : 1.0f;
    gemm_body(A, W, bi, out, z, cosT, sinT, scale, sm);
}

__global__ __launch_bounds__(128, 2)
void gemm_out(const float* __restrict__ A, const float* __restrict__ W,
              const float* __restrict__ bias, float* __restrict__ out)
{
    extern __shared__ float sm[];
    gemm_body(A, W, bias, out, 3, nullptr, nullptr, 1.0f, sm);
}

// ---------------------------------------------------------------------------
// Flash attention (R9): q-tile 128, warp owns 32 q-rows, fixed-max softmax.
// smem: QT[128][68] | Kb0[64][68] | Kb1 | Vl[64][68] | VT[64][68] = 104448 B
// ---------------------------------------------------------------------------
constexpr int AP = 68;
constexpr int QT_F = 128 * AP;
constexpr int KV_F = 64 * AP;
constexpr int SMEM_FLASH = (QT_F + 4 * KV_F) * 4;  // 104448 B

__global__ __launch_bounds__(128, 2)
void attn_flash(const float* __restrict__ Q,
                const float* __restrict__ K,
                const float* __restrict__ V,
                float* __restrict__ ctx,
                const float* __restrict__ tempPtr)
{
    extern __shared__ float smf[];
    float* QT  = smf;
    float* Kb0 = smf + QT_F;
    float* Kb1 = Kb0 + KV_F;
    float* Vl  = Kb1 + KV_F;
    float* VT  = Vl + KV_F;

    const int tid = threadIdx.x;
    const int lane = tid & 31;
    const int warp = tid >> 5;
    const int g = lane >> 2;
    const int t = lane & 3;
    const int qt = blockIdx.x;
    const int bh = blockIdx.y;
    const int bb = bh >> 4;
    const int hh = bh & 15;
    const size_t head_off = (size_t)bh * Sc * Dc;
    const float M = fabsf(*tempPtr);

    const int lr8 = ((lane >> 3) & 1) * 8 + (lane & 7);
    const int lc4 = (lane >> 4) * 4;
    const int br16 = (lane >> 4) * 8 + (lane & 7);
    const int bc4 = ((lane >> 3) & 1) * 4;

    const int vd4 = tid >> 3;
    const int vr0 = tid & 7;

    {
        const float4* src = (const float4*)(Q + head_off + (size_t)qt * 128 * Dc);
        for (int i = tid; i < 2048; i += 128) {
            const int r = i >> 4, c4 = i & 15;
            *(float4*)&QT[r * AP + c4 * 4] = src[i];
        }
    }

    {
        const float* gK = K + head_off;
        const float* gV = V + head_off;
        #pragma unroll
        for (int i = 0; i < 8; i++) {
            const int idx = tid + i * 128;
            const int r = idx >> 4, seg = idx & 15;
            cp_async16(s2u(Kb0 + r * AP + seg * 4), gK + (size_t)r * Dc + seg * 4);
            cp_async16(s2u(Vl + r * AP + seg * 4), gV + (size_t)r * Dc + seg * 4);
        }
        CP_COMMIT();
    }

    float run_s[2][2] = {{0.f, 0.f}, {0.f, 0.f}};
    float oacc[2][8][4];
    #pragma unroll
    for (int mt = 0; mt < 2; mt++)
        #pragma unroll
        for (int j = 0; j < 8; j++)
            #pragma unroll
            for (int k = 0; k < 4; k++) oacc[mt][j][k] = 0.f;

    const uint32_t fullm = 0xffffffffu;
    const int src0 = (lane & ~3) | (t >> 1);
    const int src1 = src0 + 2;
    const bool odd = (t & 1) != 0;

    for (int kt = 0; kt < 8; kt++) {
        float* Kc = (kt & 1) ? Kb1 : Kb0;
        float* Kn = (kt & 1) ? Kb0 : Kb1;

        CP_WAIT(0);
        __syncthreads();

        #pragma unroll
        for (int p = 0; p < 8; p++) {
            const int key = vr0 + 8 * p;
            float4 v = *(const float4*)&Vl[key * AP + vd4 * 4];
            VT[(vd4 * 4 + 0) * AP + key] = v.x;
            VT[(vd4 * 4 + 1) * AP + key] = v.y;
            VT[(vd4 * 4 + 2) * AP + key] = v.z;
            VT[(vd4 * 4 + 3) * AP + key] = v.w;
        }
        __syncthreads();

        if (kt < 7) {
            const float* gK = K + head_off + (size_t)(kt + 1) * 64 * Dc;
            const float* gV = V + head_off + (size_t)(kt + 1) * 64 * Dc;
            #pragma unroll
            for (int i = 0; i < 8; i++) {
                const int idx = tid + i * 128;
                const int r = idx >> 4, seg = idx & 15;
                cp_async16(s2u(Kn + r * AP + seg * 4), gK + (size_t)r * Dc + seg * 4);
                cp_async16(s2u(Vl + r * AP + seg * 4), gV + (size_t)r * Dc + seg * 4);
            }
            CP_COMMIT();
        }

        float s[2][8][4];
        #pragma unroll
        for (int mt = 0; mt < 2; mt++)
            #pragma unroll
            for (int j = 0; j < 8; j++)
                #pragma unroll
                for (int k = 0; k < 4; k++) s[mt][j][k] = 0.f;

        #pragma unroll
        for (int ks = 0; ks < 8; ks++) {
            uint32_t a[2][4], b[4][4];
            #pragma unroll
            for (int mt = 0; mt < 2; mt++)
                ldsm4(a[mt], QT + (warp * 32 + mt * 16 + lr8) * AP + ks * 8 + lc4);
            #pragma unroll
            for (int jj = 0; jj < 4; jj++)
                ldsm4(b[jj], Kc + (jj * 16 + br16) * AP + ks * 8 + bc4);
            #pragma unroll
            for (int mt = 0; mt < 2; mt++)
                #pragma unroll
                for (int jj = 0; jj < 4; jj++) {
                    mma_tf32(s[mt][2 * jj + 0], a[mt], &b[jj][0]);
                    mma_tf32(s[mt][2 * jj + 1], a[mt], &b[jj][2]);
                }
        }

        #pragma unroll
        for (int mt = 0; mt < 2; mt++) {
            #pragma unroll
            for (int j = 0; j < 8; j++) {
                float p0 = __expf(s[mt][j][0] - M);
                float p1 = __expf(s[mt][j][1] - M);
                float p2 = __expf(s[mt][j][2] - M);
                float p3 = __expf(s[mt][j][3] - M);
                run_s[mt][0] += p0 + p1;
                run_s[mt][1] += p2 + p3;
                s[mt][j][0] = tf32r(p0); s[mt][j][1] = tf32r(p1);
                s[mt][j][2] = tf32r(p2); s[mt][j][3] = tf32r(p3);
            }
        }

        #pragma unroll
        for (int k8 = 0; k8 < 8; k8++) {
            uint32_t a[2][4];
            #pragma unroll
            for (int mt = 0; mt < 2; mt++) {
                float v00 = __shfl_sync(fullm, s[mt][k8][0], src0);
                float v01 = __shfl_sync(fullm, s[mt][k8][1], src0);
                float v02 = __shfl_sync(fullm, s[mt][k8][2], src0);
                float v03 = __shfl_sync(fullm, s[mt][k8][3], src0);
                float v10 = __shfl_sync(fullm, s[mt][k8][0], src1);
                float v11 = __shfl_sync(fullm, s[mt][k8][1], src1);
                float v12 = __shfl_sync(fullm, s[mt][k8][2], src1);
                float v13 = __shfl_sync(fullm, s[mt][k8][3], src1);
                a[mt][0] = __float_as_uint(odd ? v01 : v00);
                a[mt][1] = __float_as_uint(odd ? v03 : v02);
                a[mt][2] = __float_as_uint(odd ? v11 : v10);
                a[mt][3] = __float_as_uint(odd ? v13 : v12);
            }
            #pragma unroll
            for (int dj = 0; dj < 4; dj++) {
                uint32_t b[4];
                ldsm4(b, VT + (dj * 16 + br16) * AP + k8 * 8 + bc4);
                #pragma unroll
                for (int mt = 0; mt < 2; mt++) {
                    mma_tf32(oacc[mt][2 * dj + 0], a[mt], &b[0]);
                    mma_tf32(oacc[mt][2 * dj + 1], a[mt], &b[2]);
                }
            }
        }
    }

    #pragma unroll
    for (int mt = 0; mt < 2; mt++)
        #pragma unroll
        for (int h = 0; h < 2; h++) {
            run_s[mt][h] += __shfl_xor_sync(fullm, run_s[mt][h], 1);
            run_s[mt][h] += __shfl_xor_sync(fullm, run_s[mt][h], 2);
        }

    #pragma unroll
    for (int mt = 0; mt < 2; mt++) {
        const float inv0 = 1.f / run_s[mt][0];
        const float inv1 = 1.f / run_s[mt][1];
        #pragma unroll
        for (int d8 = 0; d8 < 8; d8++) {
            const int dcol = d8 * 8 + 2 * t;
            {
                const int srow = qt * 128 + warp * 32 + mt * 16 + g;
                float2 v;
                v.x = tf32r(oacc[mt][d8][0] * inv0);
                v.y = tf32r(oacc[mt][d8][1] * inv0);
                *(float2*)&ctx[((size_t)bb * Sc + srow) * Ec + hh * Dc + dcol] = v;
            }
            {
                const int srow = qt * 128 + warp * 32 + mt * 16 + g + 8;
                float2 v;
                v.x = tf32r(oacc[mt][d8][2] * inv1);
                v.y = tf32r(oacc[mt][d8][3] * inv1);
                *(float2*)&ctx[((size_t)bb * Sc + srow) * Ec + hh * Dc + dcol] = v;
            }
        }
    }
}

// ---------------------------------------------------------------------------
extern "C" void kernel_launch(void* const* d_in, const int* in_sizes, int n_in,
                              void* d_out, int out_size)
{
    const float* x_q  = (const float*)d_in[0];
    const float* x_k  = (const float*)d_in[1];
    const float* x_v  = (const float*)d_in[2];
    const float* Wq   = (const float*)d_in[3];
    const float* bq   = (const float*)d_in[4];
    const float* Wk   = (const float*)d_in[5];
    const float* bk   = (const float*)d_in[6];
    const float* Wv   = (const float*)d_in[7];
    const float* bv   = (const float*)d_in[8];
    const float* Wo   = (const float*)d_in[9];
    const float* bo   = (const float*)d_in[10];
    const float* temp = (const float*)d_in[11];
    const float* cosT = (const float*)d_in[12];
    const float* sinT = (const float*)d_in[13];
    float* out = (float*)d_out;

    float *pQ, *pK, *pV, *pC, *cxq, *cxk, *cxv, *cwq, *cwk, *cwv, *cwo;
    cudaGetSymbolAddress((void**)&pQ, g_Q);
    cudaGetSymbolAddress((void**)&pK, g_K);
    cudaGetSymbolAddress((void**)&pV, g_V);
    cudaGetSymbolAddress((void**)&pC, g_ctx);
    cudaGetSymbolAddress((void**)&cxq, g_cxq);
    cudaGetSymbolAddress((void**)&cxk, g_cxk);
    cudaGetSymbolAddress((void**)&cxv, g_cxv);
    cudaGetSymbolAddress((void**)&cwq, g_cwq);
    cudaGetSymbolAddress((void**)&cwk, g_cwk);
    cudaGetSymbolAddress((void**)&cwv, g_cwv);
    cudaGetSymbolAddress((void**)&cwo, g_cwo);

    cudaFuncSetAttribute(gemm_qkv,
                         cudaFuncAttributeMaxDynamicSharedMemorySize, SMEM_GEMM);
    cudaFuncSetAttribute(gemm_out,
                         cudaFuncAttributeMaxDynamicSharedMemorySize, SMEM_GEMM);
    cudaFuncSetAttribute(attn_flash,
                         cudaFuncAttributeMaxDynamicSharedMemorySize, SMEM_FLASH);

    const int nx4 = Mrows * Ec / 4;   // 1M
    const int nw4 = Ec * Ec / 4;      // 256K

    cvt_all<<<dim3((nx4 + 255) / 256, 7), 256>>>(
        x_q, x_k, x_v, Wq, Wk, Wv, Wo,
        cxq, cxk, cxv, cwq, cwk, cwv, cwo, nx4, nw4);

    gemm_qkv<<<dim3(Ec / 128, Mrows / 128, 3), 128, SMEM_GEMM>>>(
        cxq, cxk, cxv, cwq, cwk, cwv, bq, bk, bv, pQ, pK, pV,
        cosT, sinT, temp);

    attn_flash<<<dim3(4, Bc * Hc), 128, SMEM_FLASH>>>(pQ, pK, pV, pC, temp);

    gemm_out<<<dim3(Ec / 128, Mrows / 128), 128, SMEM_GEMM>>>(pC, cwo, bo, out);
}

// round 12
// speedup vs baseline: 1.9290x; 1.7523x over previous
#include <cuda_runtime.h>
#include <cuda_fp16.h>
#include <math.h>
#include <cstdint>

// Problem constants
constexpr int Bc = 8;
constexpr int Sc = 512;
constexpr int Ec = 1024;
constexpr int Hc = 16;
constexpr int Dc = 64;
constexpr int Mrows = Bc * Sc;   // 4096

// Scratch (static device arrays: allocation-free). All fp16.
__device__ __half g_Q[(size_t)Mrows * Ec];
__device__ __half g_K[(size_t)Mrows * Ec];
__device__ __half g_V[(size_t)Mrows * Ec];
__device__ __half g_ctx[(size_t)Mrows * Ec];
__device__ __half g_cxq[(size_t)Mrows * Ec];
__device__ __half g_cxk[(size_t)Mrows * Ec];
__device__ __half g_cxv[(size_t)Mrows * Ec];
__device__ __half g_cwq[(size_t)Ec * Ec];
__device__ __half g_cwk[(size_t)Ec * Ec];
__device__ __half g_cwv[(size_t)Ec * Ec];
__device__ __half g_cwo[(size_t)Ec * Ec];

// ---------------------------------------------------------------------------
// helpers
// ---------------------------------------------------------------------------
__device__ __forceinline__ uint32_t s2u(const void* p) {
    uint32_t a;
    asm("{ .reg .u64 t; cvta.to.shared.u64 t, %1; cvt.u32.u64 %0, t; }"
        : "=r"(a) : "l"(p));
    return a;
}

__device__ __forceinline__ void cp_async16(uint32_t saddr, const void* gaddr) {
    asm volatile("cp.async.cg.shared.global [%0], [%1], 16;" :: "r"(saddr), "l"(gaddr));
}
#define CP_COMMIT() asm volatile("cp.async.commit_group;" ::: "memory")
#define CP_WAIT(n)  asm volatile("cp.async.wait_group %0;" :: "n"(n) : "memory")

// pack two fp32 -> half2 (lo = first arg in low 16 bits)
__device__ __forceinline__ uint32_t pack_h2(float lo, float hi) {
    uint32_t r;
    asm("cvt.rn.f16x2.f32 %0, %1, %2;" : "=r"(r) : "f"(hi), "f"(lo));
    return r;
}

__device__ __forceinline__ void mma_f16(float* d, const uint32_t* a, const uint32_t* b) {
    asm volatile(
        "mma.sync.aligned.m16n8k16.row.col.f32.f16.f16.f32 "
        "{%0,%1,%2,%3}, {%4,%5,%6,%7}, {%8,%9}, {%0,%1,%2,%3};"
        : "+f"(d[0]), "+f"(d[1]), "+f"(d[2]), "+f"(d[3])
        : "r"(a[0]), "r"(a[1]), "r"(a[2]), "r"(a[3]), "r"(b[0]), "r"(b[1]));
}

__device__ __forceinline__ void ldsm4(uint32_t* r, const void* smem_ptr) {
    uint32_t a = s2u(smem_ptr);
    asm volatile("ldmatrix.sync.aligned.m8n8.x4.shared.b16 {%0,%1,%2,%3}, [%4];"
                 : "=r"(r[0]), "=r"(r[1]), "=r"(r[2]), "=r"(r[3]) : "r"(a));
}
__device__ __forceinline__ void ldsm4t(uint32_t* r, const void* smem_ptr) {
    uint32_t a = s2u(smem_ptr);
    asm volatile("ldmatrix.sync.aligned.m8n8.x4.trans.shared.b16 {%0,%1,%2,%3}, [%4];"
                 : "=r"(r[0]), "=r"(r[1]), "=r"(r[2]), "=r"(r[3]) : "r"(a));
}

// ---------------------------------------------------------------------------
// fused fp32 -> fp16 pre-pass for all 7 tensors (grid.y selects)
// ---------------------------------------------------------------------------
__global__ void cvt_all(const float* i0, const float* i1, const float* i2,
                        const float* i3, const float* i4, const float* i5,
                        const float* i6,
                        __half* o0, __half* o1, __half* o2, __half* o3,
                        __half* o4, __half* o5, __half* o6,
                        int nx4, int nw4) {
    const int y = blockIdx.y;
    const float* in;
    __half* out;
    int n4;
    switch (y) {
        case 0: in = i0; out = o0; n4 = nx4; break;
        case 1: in = i1; out = o1; n4 = nx4; break;
        case 2: in = i2; out = o2; n4 = nx4; break;
        case 3: in = i3; out = o3; n4 = nw4; break;
        case 4: in = i4; out = o4; n4 = nw4; break;
        case 5: in = i5; out = o5; n4 = nw4; break;
        default: in = i6; out = o6; n4 = nw4; break;
    }
    int i = blockIdx.x * blockDim.x + threadIdx.x;
    if (i >= n4) return;
    float4 v = ((const float4*)in)[i];
    uint2 r;
    r.x = pack_h2(v.x, v.y);
    r.y = pack_h2(v.z, v.w);
    ((uint2*)out)[i] = r;
}

// ---------------------------------------------------------------------------
// fp16 HMMA GEMM: CTA 128x128, 128 threads (2x2 warps), warp tile 64x64,
// BK=32 halfs (2 k16-steps), 4-stage cp.async, pitch-40-half smem.
// B operand: NO-TRANS ldmatrix (W is [n][k], matching the k-major B pattern).
// mode 0: rope+l2norm+temp scatter -> half (Q)
// mode 1: rope+l2norm scatter -> half (K)
// mode 2: bias scatter -> half (V)
// mode 3: plain fp32 row-major (final out)
// ---------------------------------------------------------------------------
constexpr int BK = 32;                     // halfs per chunk
constexpr int PITCHH = 40;                 // halfs (80B rows, ldsm conflict-free)
constexpr int STAGES = 4;
constexpr int TILE_H = 128 * PITCHH;       // 5120 halfs per tile
constexpr int STAGE_H = 2 * TILE_H;        // 10240
constexpr int NCH = Ec / BK;               // 32
constexpr int SMEM_GEMM = STAGES * STAGE_H * 2;   // 81920 B

__device__ __forceinline__
void gemm_body(const __half* __restrict__ A, const __half* __restrict__ W,
               const float* __restrict__ bias, void* __restrict__ outv,
               int mode, const float* __restrict__ cosT,
               const float* __restrict__ sinT, float scale, __half* sm)
{
    const int tid = threadIdx.x;
    const int lane = tid & 31;
    const int wid = tid >> 5;
    const int warp_m = wid >> 1;          // 0..1
    const int warp_n = wid & 1;           // 0..1
    const int g = lane >> 2;
    const int t = lane & 3;
    const int m0 = blockIdx.y * 128;
    const int n0 = blockIdx.x * 128;

    // ldmatrix lane address components (A-style no-trans for both A and B)
    const int aRow = warp_m * 64 + (lane & 15);                  // + mt*16
    const int aKoff = (lane >> 4) * 8;
    const int bN = warp_n * 64 + (lane & 7) + (lane >> 4) * 8;   // + pair*16
    const int bKoff = ((lane >> 3) & 1) * 8;

    float d[4][8][4];
    #pragma unroll
    for (int i = 0; i < 4; i++)
        #pragma unroll
        for (int j = 0; j < 8; j++)
            #pragma unroll
            for (int k = 0; k < 4; k++) d[i][j][k] = 0.f;

    const __half* gA0 = A + (size_t)m0 * Ec;
    const __half* gW0 = W + (size_t)n0 * Ec;

    auto load_stage = [&](int c) {
        __half* As = sm + (c % STAGES) * STAGE_H;
        __half* Bs = As + TILE_H;
        const __half* gA = gA0 + c * BK;
        const __half* gW = gW0 + c * BK;
        #pragma unroll
        for (int i = 0; i < 4; i++) {
            const int idx = tid + i * 128;       // 0..511
            const int row = idx >> 2, seg = idx & 3;
            cp_async16(s2u(As + row * PITCHH + seg * 8),
                       gA + (size_t)row * Ec + seg * 8);
            cp_async16(s2u(Bs + row * PITCHH + seg * 8),
                       gW + (size_t)row * Ec + seg * 8);
        }
    };

    load_stage(0); CP_COMMIT();
    load_stage(1); CP_COMMIT();
    load_stage(2); CP_COMMIT();

    for (int c = 0; c < NCH; c++) {
        const int pend = (NCH - 1 - c < 2) ? (NCH - 1 - c) : 2;
        if (pend == 2) { CP_WAIT(2); } else if (pend == 1) { CP_WAIT(1); }
        else { CP_WAIT(0); }
        __syncthreads();

        if (c + 3 < NCH) { load_stage(c + 3); CP_COMMIT(); }

        const __half* As = sm + (c % STAGES) * STAGE_H;
        const __half* Bs = As + TILE_H;

        #pragma unroll
        for (int ks = 0; ks < 2; ks++) {
            uint32_t a[4][4], b[4][4];
            #pragma unroll
            for (int mt = 0; mt < 4; mt++)
                ldsm4(a[mt], As + (aRow + mt * 16) * PITCHH + ks * 16 + aKoff);
            #pragma unroll
            for (int p = 0; p < 4; p++)
                ldsm4(b[p], Bs + (bN + p * 16) * PITCHH + ks * 16 + bKoff);
            #pragma unroll
            for (int mt = 0; mt < 4; mt++)
                #pragma unroll
                for (int p = 0; p < 4; p++) {
                    mma_f16(d[mt][2 * p + 0], a[mt], &b[p][0]);
                    mma_f16(d[mt][2 * p + 1], a[mt], &b[p][2]);
                }
        }
    }

    const uint32_t fullm = 0xffffffffu;

    if (mode <= 1) {
        __half* out = (__half*)outv;
        #pragma unroll
        for (int mt = 0; mt < 4; mt++) {
            const int m_g = m0 + warp_m * 64 + mt * 16 + g;
            const int s0 = m_g & (Sc - 1);
            const int s1 = (m_g + 8) & (Sc - 1);
            float2 r0v[8], r1v[8];
            float ss0 = 0.f, ss1 = 0.f;
            #pragma unroll
            for (int nt = 0; nt < 8; nt++) {
                const int ncol = n0 + warp_n * 64 + nt * 8 + 2 * t;
                const int j = (ncol & 63) >> 1;
                const float b0 = bias[ncol], b1 = bias[ncol + 1];
                const float c0 = cosT[s0 * 32 + j], sn0 = sinT[s0 * 32 + j];
                const float c1 = cosT[s1 * 32 + j], sn1 = sinT[s1 * 32 + j];
                {
                    const float x = d[mt][nt][0] + b0;
                    const float y = d[mt][nt][1] + b1;
                    const float rx = x * c0 - y * sn0;
                    const float ry = x * sn0 + y * c0;
                    ss0 += rx * rx + ry * ry;
                    r0v[nt] = make_float2(rx, ry);
                }
                {
                    const float x = d[mt][nt][2] + b0;
                    const float y = d[mt][nt][3] + b1;
                    const float rx = x * c1 - y * sn1;
                    const float ry = x * sn1 + y * c1;
                    ss1 += rx * rx + ry * ry;
                    r1v[nt] = make_float2(rx, ry);
                }
            }
            ss0 += __shfl_xor_sync(fullm, ss0, 1);
            ss0 += __shfl_xor_sync(fullm, ss0, 2);
            ss1 += __shfl_xor_sync(fullm, ss1, 1);
            ss1 += __shfl_xor_sync(fullm, ss1, 2);
            const float inv0 = scale / fmaxf(sqrtf(ss0), 1e-12f);
            const float inv1 = scale / fmaxf(sqrtf(ss1), 1e-12f);

            #pragma unroll
            for (int nt = 0; nt < 8; nt++) {
                const int ncol = n0 + warp_n * 64 + nt * 8 + 2 * t;
                const int hh = ncol >> 6, dd = ncol & (Dc - 1);
                {
                    const int bb = m_g >> 9;
                    *(uint32_t*)&out[((((size_t)bb * Hc + hh) * Sc + s0) << 6) + dd] =
                        pack_h2(r0v[nt].x * inv0, r0v[nt].y * inv0);
                }
                {
                    const int bb = (m_g + 8) >> 9;
                    *(uint32_t*)&out[((((size_t)bb * Hc + hh) * Sc + s1) << 6) + dd] =
                        pack_h2(r1v[nt].x * inv1, r1v[nt].y * inv1);
                }
            }
        }
    } else if (mode == 2) {
        __half* out = (__half*)outv;
        #pragma unroll
        for (int mt = 0; mt < 4; mt++) {
            #pragma unroll
            for (int nt = 0; nt < 8; nt++) {
                const int n = n0 + warp_n * 64 + nt * 8 + 2 * t;
                const float b0 = bias[n], b1 = bias[n + 1];
                #pragma unroll
                for (int half = 0; half < 2; half++) {
                    const int m = m0 + warp_m * 64 + mt * 16 + g + half * 8;
                    const int bb = m >> 9, ss = m & (Sc - 1);
                    const int hh = n >> 6, dd = n & (Dc - 1);
                    *(uint32_t*)&out[((((size_t)bb * Hc + hh) * Sc + ss) << 6) + dd] =
                        pack_h2(d[mt][nt][half * 2 + 0] + b0,
                                d[mt][nt][half * 2 + 1] + b1);
                }
            }
        }
    } else {
        float* out = (float*)outv;
        #pragma unroll
        for (int mt = 0; mt < 4; mt++) {
            #pragma unroll
            for (int nt = 0; nt < 8; nt++) {
                const int n = n0 + warp_n * 64 + nt * 8 + 2 * t;
                const float b0 = bias[n], b1 = bias[n + 1];
                #pragma unroll
                for (int half = 0; half < 2; half++) {
                    const int m = m0 + warp_m * 64 + mt * 16 + g + half * 8;
                    float2 v;
                    v.x = d[mt][nt][half * 2 + 0] + b0;
                    v.y = d[mt][nt][half * 2 + 1] + b1;
                    *(float2*)&out[(size_t)m * Ec + n] = v;
                }
            }
        }
    }
}

__global__ __launch_bounds__(128, 2)
void gemm_qkv(const __half* A0, const __half* A1, const __half* A2,
              const __half* W0, const __half* W1, const __half* W2,
              const float* b0, const float* b1, const float* b2,
              __half* o0, __half* o1, __half* o2,
              const float* cosT, const float* sinT, const float* tempPtr)
{
    extern __shared__ __half smh[];
    const int z = blockIdx.z;
    const __half* A = z == 0 ? A0 : z == 1 ? A1 : A2;
    const __half* W = z == 0 ? W0 : z == 1 ? W1 : W2;
    const float* bi = z == 0 ? b0 : z == 1 ? b1 : b2;
    __half* out = z == 0 ? o0 : z == 1 ? o1 : o2;
    const float scale = (z == 0) ? *tempPtr : 1.0f;
    gemm_body(A, W, bi, out, z, cosT, sinT, scale, smh);
}

__global__ __launch_bounds__(128, 2)
void gemm_out(const __half* __restrict__ A, const __half* __restrict__ W,
              const float* __restrict__ bias, float* __restrict__ out)
{
    extern __shared__ __half smh[];
    gemm_body(A, W, bias, out, 3, nullptr, nullptr, 1.0f, smh);
}

// ---------------------------------------------------------------------------
// fp16 flash attention: q-tile 128, 128 threads, warp owns 32 q-rows.
// Fixed-max softmax (|score| <= |temp|). K and V double-buffered via cp.async.
// QK^T B-frags: NO-TRANS ldmatrix on K[key][d]; PV B-frags: TRANS ldmatrix on
// V[key][d]; probs pack per-thread into fp16 A-frags (no shuffles).
// smem: QT[128][72] | Kb0 | Kb1 | Vb0 | Vb1 (64x72 each) = 55296 B
// ---------------------------------------------------------------------------
constexpr int APH = 72;                    // halfs (144B rows)
constexpr int QT_H = 128 * APH;            // 9216 halfs
constexpr int KV_H = 64 * APH;             // 4608 halfs
constexpr int SMEM_FLASH = (QT_H + 4 * KV_H) * 2;  // 55296 B

__global__ __launch_bounds__(128, 2)
void attn_flash(const __half* __restrict__ Q,
                const __half* __restrict__ K,
                const __half* __restrict__ V,
                __half* __restrict__ ctx,
                const float* __restrict__ tempPtr)
{
    extern __shared__ __half smh[];
    __half* QT  = smh;
    __half* Kb0 = smh + QT_H;
    __half* Kb1 = Kb0 + KV_H;
    __half* Vb0 = Kb1 + KV_H;
    __half* Vb1 = Vb0 + KV_H;

    const int tid = threadIdx.x;
    const int lane = tid & 31;
    const int warp = tid >> 5;
    const int g = lane >> 2;
    const int t = lane & 3;
    const int qt = blockIdx.x;
    const int bh = blockIdx.y;
    const int bb = bh >> 4;
    const int hh = bh & 15;
    const size_t head_off = (size_t)bh * Sc * Dc;
    const float M = fabsf(*tempPtr);

    // ldmatrix lane components
    const int qRow = warp * 32 + (lane & 15);                    // + mt*16 (no-trans A)
    const int qKoff = (lane >> 4) * 8;
    const int kKey = (lane & 7) + (lane >> 4) * 8;               // + pair*16 (no-trans B)
    const int kDoff = ((lane >> 3) & 1) * 8;
    const int vKey = lane & 15;                                  // + kstep*16 (TRANS B)
    const int vDoff = (lane >> 4) * 8;                           // + dpair*16

    // ---- load Q tile [128][64] halfs ----
    {
        const __half* gQ = Q + head_off + (size_t)qt * 128 * Dc;
        for (int i = tid; i < 1024; i += 128) {
            const int r = i >> 3, s = i & 7;
            *(uint4*)&QT[r * APH + s * 8] = *(const uint4*)&gQ[r * Dc + s * 8];
        }
    }

    // ---- prefetch K/V chunk 0 ----
    {
        const __half* gK = K + head_off;
        const __half* gV = V + head_off;
        #pragma unroll
        for (int i = 0; i < 4; i++) {
            const int idx = tid + i * 128;       // 0..511
            const int r = idx >> 3, s = idx & 7;
            cp_async16(s2u(Kb0 + r * APH + s * 8), gK + (size_t)r * Dc + s * 8);
            cp_async16(s2u(Vb0 + r * APH + s * 8), gV + (size_t)r * Dc + s * 8);
        }
        CP_COMMIT();
    }

    float run_s[2][2] = {{0.f, 0.f}, {0.f, 0.f}};
    float oacc[2][8][4];
    #pragma unroll
    for (int mt = 0; mt < 2; mt++)
        #pragma unroll
        for (int j = 0; j < 8; j++)
            #pragma unroll
            for (int k = 0; k < 4; k++) oacc[mt][j][k] = 0.f;

    const uint32_t fullm = 0xffffffffu;

    for (int kt = 0; kt < 8; kt++) {
        __half* Kc = (kt & 1) ? Kb1 : Kb0;
        __half* Vc = (kt & 1) ? Vb1 : Vb0;
        __half* Kn = (kt & 1) ? Kb0 : Kb1;
        __half* Vn = (kt & 1) ? Vb0 : Vb1;

        CP_WAIT(0);
        __syncthreads();     // chunk kt ready; all warps done with kt-1 buffers

        if (kt < 7) {
            const __half* gK = K + head_off + (size_t)(kt + 1) * 64 * Dc;
            const __half* gV = V + head_off + (size_t)(kt + 1) * 64 * Dc;
            #pragma unroll
            for (int i = 0; i < 4; i++) {
                const int idx = tid + i * 128;
                const int r = idx >> 3, s = idx & 7;
                cp_async16(s2u(Kn + r * APH + s * 8), gK + (size_t)r * Dc + s * 8);
                cp_async16(s2u(Vn + r * APH + s * 8), gV + (size_t)r * Dc + s * 8);
            }
            CP_COMMIT();
        }

        // ---- QK^T: 32 q-rows x 64 keys (k-dim = d = 4 k16-steps) ----
        float s[2][8][4];
        #pragma unroll
        for (int mt = 0; mt < 2; mt++)
            #pragma unroll
            for (int j = 0; j < 8; j++)
                #pragma unroll
                for (int k = 0; k < 4; k++) s[mt][j][k] = 0.f;

        #pragma unroll
        for (int ks = 0; ks < 4; ks++) {
            uint32_t a[2][4], b[4][4];
            #pragma unroll
            for (int mt = 0; mt < 2; mt++)
                ldsm4(a[mt], QT + (qRow + mt * 16) * APH + ks * 16 + qKoff);
            #pragma unroll
            for (int p = 0; p < 4; p++)
                ldsm4(b[p], Kc + (kKey + p * 16) * APH + ks * 16 + kDoff);
            #pragma unroll
            for (int mt = 0; mt < 2; mt++)
                #pragma unroll
                for (int p = 0; p < 4; p++) {
                    mma_f16(s[mt][2 * p + 0], a[mt], &b[p][0]);
                    mma_f16(s[mt][2 * p + 1], a[mt], &b[p][2]);
                }
        }

        // ---- fixed-max softmax: p = exp(s - M), per-lane partial sums ----
        #pragma unroll
        for (int mt = 0; mt < 2; mt++) {
            #pragma unroll
            for (int j = 0; j < 8; j++) {
                float p0 = __expf(s[mt][j][0] - M);
                float p1 = __expf(s[mt][j][1] - M);
                float p2 = __expf(s[mt][j][2] - M);
                float p3 = __expf(s[mt][j][3] - M);
                run_s[mt][0] += p0 + p1;
                run_s[mt][1] += p2 + p3;
                s[mt][j][0] = p0; s[mt][j][1] = p1;
                s[mt][j][2] = p2; s[mt][j][3] = p3;
            }
        }

        // ---- PV: A-frags packed per-thread from prob C-frags (no shuffles) ----
        #pragma unroll
        for (int kk = 0; kk < 4; kk++) {       // key k16-steps
            uint32_t a[2][4];
            #pragma unroll
            for (int mt = 0; mt < 2; mt++) {
                a[mt][0] = pack_h2(s[mt][2 * kk][0], s[mt][2 * kk][1]);
                a[mt][1] = pack_h2(s[mt][2 * kk][2], s[mt][2 * kk][3]);
                a[mt][2] = pack_h2(s[mt][2 * kk + 1][0], s[mt][2 * kk + 1][1]);
                a[mt][3] = pack_h2(s[mt][2 * kk + 1][2], s[mt][2 * kk + 1][3]);
            }
            #pragma unroll
            for (int p = 0; p < 4; p++) {      // d-pairs (2 d-tiles each)
                uint32_t b[4];
                ldsm4t(b, Vc + (kk * 16 + vKey) * APH + p * 16 + vDoff);
                #pragma unroll
                for (int mt = 0; mt < 2; mt++) {
                    mma_f16(oacc[mt][2 * p + 0], a[mt], &b[0]);
                    mma_f16(oacc[mt][2 * p + 1], a[mt], &b[2]);
                }
            }
        }
    }

    // ---- reduce row sums across quad ----
    #pragma unroll
    for (int mt = 0; mt < 2; mt++)
        #pragma unroll
        for (int h = 0; h < 2; h++) {
            run_s[mt][h] += __shfl_xor_sync(fullm, run_s[mt][h], 1);
            run_s[mt][h] += __shfl_xor_sync(fullm, run_s[mt][h], 2);
        }

    // ---- epilogue: normalize, store ctx[b][s][h*64+d] as half ----
    #pragma unroll
    for (int mt = 0; mt < 2; mt++) {
        const float inv0 = 1.f / run_s[mt][0];
        const float inv1 = 1.f / run_s[mt][1];
        #pragma unroll
        for (int d8 = 0; d8 < 8; d8++) {
            const int dcol = d8 * 8 + 2 * t;
            {
                const int srow = qt * 128 + warp * 32 + mt * 16 + g;
                *(uint32_t*)&ctx[((size_t)bb * Sc + srow) * Ec + hh * Dc + dcol] =
                    pack_h2(oacc[mt][d8][0] * inv0, oacc[mt][d8][1] * inv0);
            }
            {
                const int srow = qt * 128 + warp * 32 + mt * 16 + g + 8;
                *(uint32_t*)&ctx[((size_t)bb * Sc + srow) * Ec + hh * Dc + dcol] =
                    pack_h2(oacc[mt][d8][2] * inv1, oacc[mt][d8][3] * inv1);
            }
        }
    }
}

// ---------------------------------------------------------------------------
extern "C" void kernel_launch(void* const* d_in, const int* in_sizes, int n_in,
                              void* d_out, int out_size)
{
    const float* x_q  = (const float*)d_in[0];
    const float* x_k  = (const float*)d_in[1];
    const float* x_v  = (const float*)d_in[2];
    const float* Wq   = (const float*)d_in[3];
    const float* bq   = (const float*)d_in[4];
    const float* Wk   = (const float*)d_in[5];
    const float* bk   = (const float*)d_in[6];
    const float* Wv   = (const float*)d_in[7];
    const float* bv   = (const float*)d_in[8];
    const float* Wo   = (const float*)d_in[9];
    const float* bo   = (const float*)d_in[10];
    const float* temp = (const float*)d_in[11];
    const float* cosT = (const float*)d_in[12];
    const float* sinT = (const float*)d_in[13];
    float* out = (float*)d_out;

    __half *pQ, *pK, *pV, *pC, *cxq, *cxk, *cxv, *cwq, *cwk, *cwv, *cwo;
    cudaGetSymbolAddress((void**)&pQ, g_Q);
    cudaGetSymbolAddress((void**)&pK, g_K);
    cudaGetSymbolAddress((void**)&pV, g_V);
    cudaGetSymbolAddress((void**)&pC, g_ctx);
    cudaGetSymbolAddress((void**)&cxq, g_cxq);
    cudaGetSymbolAddress((void**)&cxk, g_cxk);
    cudaGetSymbolAddress((void**)&cxv, g_cxv);
    cudaGetSymbolAddress((void**)&cwq, g_cwq);
    cudaGetSymbolAddress((void**)&cwk, g_cwk);
    cudaGetSymbolAddress((void**)&cwv, g_cwv);
    cudaGetSymbolAddress((void**)&cwo, g_cwo);

    cudaFuncSetAttribute(gemm_qkv,
                         cudaFuncAttributeMaxDynamicSharedMemorySize, SMEM_GEMM);
    cudaFuncSetAttribute(gemm_out,
                         cudaFuncAttributeMaxDynamicSharedMemorySize, SMEM_GEMM);
    cudaFuncSetAttribute(attn_flash,
                         cudaFuncAttributeMaxDynamicSharedMemorySize, SMEM_FLASH);

    const int nx4 = Mrows * Ec / 4;   // 1M
    const int nw4 = Ec * Ec / 4;      // 256K

    cvt_all<<<dim3((nx4 + 255) / 256, 7), 256>>>(
        x_q, x_k, x_v, Wq, Wk, Wv, Wo,
        cxq, cxk, cxv, cwq, cwk, cwv, cwo, nx4, nw4);

    gemm_qkv<<<dim3(Ec / 128, Mrows / 128, 3), 128, SMEM_GEMM>>>(
        cxq, cxk, cxv, cwq, cwk, cwv, bq, bk, bv, pQ, pK, pV,
        cosT, sinT, temp);

    attn_flash<<<dim3(4, Bc * Hc), 128, SMEM_FLASH>>>(pQ, pK, pV, pC, temp);

    gemm_out<<<dim3(Ec / 128, Mrows / 128), 128, SMEM_GEMM>>>(pC, cwo, bo, out);
}

// round 13
// speedup vs baseline: 2.0173x; 1.0458x over previous
#include <cuda_runtime.h>
#include <cuda_fp16.h>
#include <math.h>
#include <cstdint>

// Problem constants
constexpr int Bc = 8;
constexpr int Sc = 512;
constexpr int Ec = 1024;
constexpr int Hc = 16;
constexpr int Dc = 64;
constexpr int Mrows = Bc * Sc;   // 4096

// Scratch (static device arrays: allocation-free). All fp16.
__device__ __half g_Q[(size_t)Mrows * Ec];
__device__ __half g_K[(size_t)Mrows * Ec];
__device__ __half g_V[(size_t)Mrows * Ec];
__device__ __half g_ctx[(size_t)Mrows * Ec];
__device__ __half g_cxq[(size_t)Mrows * Ec];
__device__ __half g_cxk[(size_t)Mrows * Ec];
__device__ __half g_cxv[(size_t)Mrows * Ec];
__device__ __half g_cwq[(size_t)Ec * Ec];
__device__ __half g_cwk[(size_t)Ec * Ec];
__device__ __half g_cwv[(size_t)Ec * Ec];
__device__ __half g_cwo[(size_t)Ec * Ec];

// ---------------------------------------------------------------------------
// helpers
// ---------------------------------------------------------------------------
__device__ __forceinline__ uint32_t s2u(const void* p) {
    uint32_t a;
    asm("{ .reg .u64 t; cvta.to.shared.u64 t, %1; cvt.u32.u64 %0, t; }"
        : "=r"(a) : "l"(p));
    return a;
}

__device__ __forceinline__ void cp_async16(uint32_t saddr, const void* gaddr) {
    asm volatile("cp.async.cg.shared.global [%0], [%1], 16;" :: "r"(saddr), "l"(gaddr));
}
#define CP_COMMIT() asm volatile("cp.async.commit_group;" ::: "memory")
#define CP_WAIT(n)  asm volatile("cp.async.wait_group %0;" :: "n"(n) : "memory")

// pack two fp32 -> half2 (lo = first arg in low 16 bits)
__device__ __forceinline__ uint32_t pack_h2(float lo, float hi) {
    uint32_t r;
    asm("cvt.rn.f16x2.f32 %0, %1, %2;" : "=r"(r) : "f"(hi), "f"(lo));
    return r;
}

__device__ __forceinline__ void mma_f16(float* d, const uint32_t* a, const uint32_t* b) {
    asm volatile(
        "mma.sync.aligned.m16n8k16.row.col.f32.f16.f16.f32 "
        "{%0,%1,%2,%3}, {%4,%5,%6,%7}, {%8,%9}, {%0,%1,%2,%3};"
        : "+f"(d[0]), "+f"(d[1]), "+f"(d[2]), "+f"(d[3])
        : "r"(a[0]), "r"(a[1]), "r"(a[2]), "r"(a[3]), "r"(b[0]), "r"(b[1]));
}

__device__ __forceinline__ void ldsm4(uint32_t* r, const void* smem_ptr) {
    uint32_t a = s2u(smem_ptr);
    asm volatile("ldmatrix.sync.aligned.m8n8.x4.shared.b16 {%0,%1,%2,%3}, [%4];"
                 : "=r"(r[0]), "=r"(r[1]), "=r"(r[2]), "=r"(r[3]) : "r"(a));
}
__device__ __forceinline__ void ldsm4t(uint32_t* r, const void* smem_ptr) {
    uint32_t a = s2u(smem_ptr);
    asm volatile("ldmatrix.sync.aligned.m8n8.x4.trans.shared.b16 {%0,%1,%2,%3}, [%4];"
                 : "=r"(r[0]), "=r"(r[1]), "=r"(r[2]), "=r"(r[3]) : "r"(a));
}

// ---------------------------------------------------------------------------
// fused fp32 -> fp16 pre-pass for all 7 tensors (grid.y selects)
// ---------------------------------------------------------------------------
__global__ void cvt_all(const float* i0, const float* i1, const float* i2,
                        const float* i3, const float* i4, const float* i5,
                        const float* i6,
                        __half* o0, __half* o1, __half* o2, __half* o3,
                        __half* o4, __half* o5, __half* o6,
                        int nx4, int nw4) {
    const int y = blockIdx.y;
    const float* in;
    __half* out;
    int n4;
    switch (y) {
        case 0: in = i0; out = o0; n4 = nx4; break;
        case 1: in = i1; out = o1; n4 = nx4; break;
        case 2: in = i2; out = o2; n4 = nx4; break;
        case 3: in = i3; out = o3; n4 = nw4; break;
        case 4: in = i4; out = o4; n4 = nw4; break;
        case 5: in = i5; out = o5; n4 = nw4; break;
        default: in = i6; out = o6; n4 = nw4; break;
    }
    int i = blockIdx.x * blockDim.x + threadIdx.x;
    if (i >= n4) return;
    float4 v = ((const float4*)in)[i];
    uint2 r;
    r.x = pack_h2(v.x, v.y);
    r.y = pack_h2(v.z, v.w);
    ((uint2*)out)[i] = r;
}

// ---------------------------------------------------------------------------
// fp16 HMMA GEMM: CTA 128x128, 128 threads (2x2 warps), warp tile 64x64,
// BK=64 halfs (4 k16-steps per chunk -> 16 barrier rounds), 3-stage cp.async,
// pitch-72-half smem. B operand: NO-TRANS ldmatrix (W is [n][k]).
// mode 0: rope+l2norm+temp scatter -> half (Q)
// mode 1: rope+l2norm scatter -> half (K)
// mode 2: bias scatter -> half (V)
// mode 3: plain fp32 row-major (final out)
// ---------------------------------------------------------------------------
constexpr int BKH = 64;                    // halfs per chunk
constexpr int PITCHH = 72;                 // halfs (144B rows; 144%128==16 -> ok)
constexpr int STAGES = 3;
constexpr int TILE_H = 128 * PITCHH;       // 9216 halfs per tile
constexpr int STAGE_H = 2 * TILE_H;        // 18432
constexpr int NCH = Ec / BKH;              // 16
constexpr int SMEM_GEMM = STAGES * STAGE_H * 2;   // 110592 B

__device__ __forceinline__
void gemm_body(const __half* __restrict__ A, const __half* __restrict__ W,
               const float* __restrict__ bias, void* __restrict__ outv,
               int mode, const float* __restrict__ cosT,
               const float* __restrict__ sinT, float scale, __half* sm)
{
    const int tid = threadIdx.x;
    const int lane = tid & 31;
    const int wid = tid >> 5;
    const int warp_m = wid >> 1;          // 0..1
    const int warp_n = wid & 1;           // 0..1
    const int g = lane >> 2;
    const int t = lane & 3;
    const int m0 = blockIdx.y * 128;
    const int n0 = blockIdx.x * 128;

    // ldmatrix lane address components (no-trans for both A and B)
    const int aRow = warp_m * 64 + (lane & 15);                  // + mt*16
    const int aKoff = (lane >> 4) * 8;
    const int bN = warp_n * 64 + (lane & 7) + (lane >> 4) * 8;   // + pair*16
    const int bKoff = ((lane >> 3) & 1) * 8;

    float d[4][8][4];
    #pragma unroll
    for (int i = 0; i < 4; i++)
        #pragma unroll
        for (int j = 0; j < 8; j++)
            #pragma unroll
            for (int k = 0; k < 4; k++) d[i][j][k] = 0.f;

    const __half* gA0 = A + (size_t)m0 * Ec;
    const __half* gW0 = W + (size_t)n0 * Ec;

    auto load_stage = [&](int c) {
        __half* As = sm + (c % STAGES) * STAGE_H;
        __half* Bs = As + TILE_H;
        const __half* gA = gA0 + c * BKH;
        const __half* gW = gW0 + c * BKH;
        #pragma unroll
        for (int i = 0; i < 8; i++) {
            const int idx = tid + i * 128;       // 0..1023
            const int row = idx >> 3, seg = idx & 7;
            cp_async16(s2u(As + row * PITCHH + seg * 8),
                       gA + (size_t)row * Ec + seg * 8);
            cp_async16(s2u(Bs + row * PITCHH + seg * 8),
                       gW + (size_t)row * Ec + seg * 8);
        }
    };

    load_stage(0); CP_COMMIT();
    load_stage(1); CP_COMMIT();

    for (int c = 0; c < NCH; c++) {
        if (c + 1 < NCH) { CP_WAIT(1); } else { CP_WAIT(0); }
        __syncthreads();   // chunk c ready; all warps done with chunk c-1

        if (c + 2 < NCH) { load_stage(c + 2); CP_COMMIT(); }

        const __half* As = sm + (c % STAGES) * STAGE_H;
        const __half* Bs = As + TILE_H;

        #pragma unroll
        for (int ks = 0; ks < 4; ks++) {
            uint32_t a[4][4], b[4][4];
            #pragma unroll
            for (int mt = 0; mt < 4; mt++)
                ldsm4(a[mt], As + (aRow + mt * 16) * PITCHH + ks * 16 + aKoff);
            #pragma unroll
            for (int p = 0; p < 4; p++)
                ldsm4(b[p], Bs + (bN + p * 16) * PITCHH + ks * 16 + bKoff);
            #pragma unroll
            for (int mt = 0; mt < 4; mt++)
                #pragma unroll
                for (int p = 0; p < 4; p++) {
                    mma_f16(d[mt][2 * p + 0], a[mt], &b[p][0]);
                    mma_f16(d[mt][2 * p + 1], a[mt], &b[p][2]);
                }
        }
    }

    const uint32_t fullm = 0xffffffffu;

    if (mode <= 1) {
        __half* out = (__half*)outv;
        #pragma unroll
        for (int mt = 0; mt < 4; mt++) {
            const int m_g = m0 + warp_m * 64 + mt * 16 + g;
            const int s0 = m_g & (Sc - 1);
            const int s1 = (m_g + 8) & (Sc - 1);
            float2 r0v[8], r1v[8];
            float ss0 = 0.f, ss1 = 0.f;
            #pragma unroll
            for (int nt = 0; nt < 8; nt++) {
                const int ncol = n0 + warp_n * 64 + nt * 8 + 2 * t;
                const int j = (ncol & 63) >> 1;
                const float b0 = bias[ncol], b1 = bias[ncol + 1];
                const float c0 = cosT[s0 * 32 + j], sn0 = sinT[s0 * 32 + j];
                const float c1 = cosT[s1 * 32 + j], sn1 = sinT[s1 * 32 + j];
                {
                    const float x = d[mt][nt][0] + b0;
                    const float y = d[mt][nt][1] + b1;
                    const float rx = x * c0 - y * sn0;
                    const float ry = x * sn0 + y * c0;
                    ss0 += rx * rx + ry * ry;
                    r0v[nt] = make_float2(rx, ry);
                }
                {
                    const float x = d[mt][nt][2] + b0;
                    const float y = d[mt][nt][3] + b1;
                    const float rx = x * c1 - y * sn1;
                    const float ry = x * sn1 + y * c1;
                    ss1 += rx * rx + ry * ry;
                    r1v[nt] = make_float2(rx, ry);
                }
            }
            ss0 += __shfl_xor_sync(fullm, ss0, 1);
            ss0 += __shfl_xor_sync(fullm, ss0, 2);
            ss1 += __shfl_xor_sync(fullm, ss1, 1);
            ss1 += __shfl_xor_sync(fullm, ss1, 2);
            const float inv0 = scale / fmaxf(sqrtf(ss0), 1e-12f);
            const float inv1 = scale / fmaxf(sqrtf(ss1), 1e-12f);

            #pragma unroll
            for (int nt = 0; nt < 8; nt++) {
                const int ncol = n0 + warp_n * 64 + nt * 8 + 2 * t;
                const int hh = ncol >> 6, dd = ncol & (Dc - 1);
                {
                    const int bb = m_g >> 9;
                    *(uint32_t*)&out[((((size_t)bb * Hc + hh) * Sc + s0) << 6) + dd] =
                        pack_h2(r0v[nt].x * inv0, r0v[nt].y * inv0);
                }
                {
                    const int bb = (m_g + 8) >> 9;
                    *(uint32_t*)&out[((((size_t)bb * Hc + hh) * Sc + s1) << 6) + dd] =
                        pack_h2(r1v[nt].x * inv1, r1v[nt].y * inv1);
                }
            }
        }
    } else if (mode == 2) {
        __half* out = (__half*)outv;
        #pragma unroll
        for (int mt = 0; mt < 4; mt++) {
            #pragma unroll
            for (int nt = 0; nt < 8; nt++) {
                const int n = n0 + warp_n * 64 + nt * 8 + 2 * t;
                const float b0 = bias[n], b1 = bias[n + 1];
                #pragma unroll
                for (int half = 0; half < 2; half++) {
                    const int m = m0 + warp_m * 64 + mt * 16 + g + half * 8;
                    const int bb = m >> 9, ss = m & (Sc - 1);
                    const int hh = n >> 6, dd = n & (Dc - 1);
                    *(uint32_t*)&out[((((size_t)bb * Hc + hh) * Sc + ss) << 6) + dd] =
                        pack_h2(d[mt][nt][half * 2 + 0] + b0,
                                d[mt][nt][half * 2 + 1] + b1);
                }
            }
        }
    } else {
        float* out = (float*)outv;
        #pragma unroll
        for (int mt = 0; mt < 4; mt++) {
            #pragma unroll
            for (int nt = 0; nt < 8; nt++) {
                const int n = n0 + warp_n * 64 + nt * 8 + 2 * t;
                const float b0 = bias[n], b1 = bias[n + 1];
                #pragma unroll
                for (int half = 0; half < 2; half++) {
                    const int m = m0 + warp_m * 64 + mt * 16 + g + half * 8;
                    float2 v;
                    v.x = d[mt][nt][half * 2 + 0] + b0;
                    v.y = d[mt][nt][half * 2 + 1] + b1;
                    *(float2*)&out[(size_t)m * Ec + n] = v;
                }
            }
        }
    }
}

__global__ __launch_bounds__(128, 2)
void gemm_qkv(const __half* A0, const __half* A1, const __half* A2,
              const __half* W0, const __half* W1, const __half* W2,
              const float* b0, const float* b1, const float* b2,
              __half* o0, __half* o1, __half* o2,
              const float* cosT, const float* sinT, const float* tempPtr)
{
    extern __shared__ __half smh[];
    const int z = blockIdx.z;
    const __half* A = z == 0 ? A0 : z == 1 ? A1 : A2;
    const __half* W = z == 0 ? W0 : z == 1 ? W1 : W2;
    const float* bi = z == 0 ? b0 : z == 1 ? b1 : b2;
    __half* out = z == 0 ? o0 : z == 1 ? o1 : o2;
    const float scale = (z == 0) ? *tempPtr : 1.0f;
    gemm_body(A, W, bi, out, z, cosT, sinT, scale, smh);
}

__global__ __launch_bounds__(128, 2)
void gemm_out(const __half* __restrict__ A, const __half* __restrict__ W,
              const float* __restrict__ bias, float* __restrict__ out)
{
    extern __shared__ __half smh[];
    gemm_body(A, W, bias, out, 3, nullptr, nullptr, 1.0f, smh);
}

// ---------------------------------------------------------------------------
// fp16 flash attention: q-tile 128, 128 threads, warp owns 32 q-rows.
// Fixed-max softmax (|score| <= |temp|). K/V prefetched in 128-key PAIRS
// (4 chunk-buffers each) -> only 4 wait+sync rounds; compute still 64-key
// granularity (register working set unchanged).
// smem: QT[128][72] | K[4][64][72] | V[4][64][72] = 92160 B
// ---------------------------------------------------------------------------
constexpr int APH = 72;                    // halfs (144B rows)
constexpr int QT_H = 128 * APH;            // 9216 halfs
constexpr int KV_H = 64 * APH;             // 4608 halfs
constexpr int SMEM_FLASH = (QT_H + 8 * KV_H) * 2;  // 92160 B

__global__ __launch_bounds__(128, 2)
void attn_flash(const __half* __restrict__ Q,
                const __half* __restrict__ K,
                const __half* __restrict__ V,
                __half* __restrict__ ctx,
                const float* __restrict__ tempPtr)
{
    extern __shared__ __half smh[];
    __half* QT = smh;
    __half* Kb = smh + QT_H;               // 4 chunk buffers
    __half* Vb = Kb + 4 * KV_H;            // 4 chunk buffers

    const int tid = threadIdx.x;
    const int lane = tid & 31;
    const int warp = tid >> 5;
    const int g = lane >> 2;
    const int t = lane & 3;
    const int qt = blockIdx.x;
    const int bh = blockIdx.y;
    const int bb = bh >> 4;
    const int hh = bh & 15;
    const size_t head_off = (size_t)bh * Sc * Dc;
    const float M = fabsf(*tempPtr);

    // ldmatrix lane components
    const int qRow = warp * 32 + (lane & 15);                    // + mt*16 (no-trans A)
    const int qKoff = (lane >> 4) * 8;
    const int kKey = (lane & 7) + (lane >> 4) * 8;               // + pair*16 (no-trans B)
    const int kDoff = ((lane >> 3) & 1) * 8;
    const int vKey = lane & 15;                                  // + kstep*16 (TRANS B)
    const int vDoff = (lane >> 4) * 8;                           // + dpair*16

    // ---- load Q tile [128][64] halfs ----
    {
        const __half* gQ = Q + head_off + (size_t)qt * 128 * Dc;
        for (int i = tid; i < 1024; i += 128) {
            const int r = i >> 3, s = i & 7;
            *(uint4*)&QT[r * APH + s * 8] = *(const uint4*)&gQ[r * Dc + s * 8];
        }
    }

    // prefetch a 128-key pair (chunks 2*pi, 2*pi+1) into chunk buffers
    auto load_pair = [&](int pi) {
        const int base = (pi & 1) * 2;     // pair-buffer -> chunk slots base, base+1
        const __half* gK = K + head_off + (size_t)pi * 128 * Dc;
        const __half* gV = V + head_off + (size_t)pi * 128 * Dc;
        #pragma unroll
        for (int i = 0; i < 8; i++) {
            const int idx = tid + i * 128;     // 0..1023 -> 128 keys x 8 segs
            const int r = idx >> 3, s = idx & 7;
            const int slot = base + (r >> 6);  // first 64 keys -> slot base
            const int rr = r & 63;
            cp_async16(s2u(Kb + slot * KV_H + rr * APH + s * 8),
                       gK + (size_t)r * Dc + s * 8);
            cp_async16(s2u(Vb + slot * KV_H + rr * APH + s * 8),
                       gV + (size_t)r * Dc + s * 8);
        }
    };

    load_pair(0); CP_COMMIT();

    float run_s[2][2] = {{0.f, 0.f}, {0.f, 0.f}};
    float oacc[2][8][4];
    #pragma unroll
    for (int mt = 0; mt < 2; mt++)
        #pragma unroll
        for (int j = 0; j < 8; j++)
            #pragma unroll
            for (int k = 0; k < 4; k++) oacc[mt][j][k] = 0.f;

    const uint32_t fullm = 0xffffffffu;

    for (int pi = 0; pi < 4; pi++) {
        CP_WAIT(0);
        __syncthreads();     // pair pi ready; all warps done with pair pi-1

        if (pi < 3) { load_pair(pi + 1); CP_COMMIT(); }

        #pragma unroll
        for (int sub = 0; sub < 2; sub++) {
            const int slot = (pi & 1) * 2 + sub;
            const __half* Kc = Kb + slot * KV_H;
            const __half* Vc = Vb + slot * KV_H;

            // ---- QK^T: 32 q-rows x 64 keys ----
            float s[2][8][4];
            #pragma unroll
            for (int mt = 0; mt < 2; mt++)
                #pragma unroll
                for (int j = 0; j < 8; j++)
                    #pragma unroll
                    for (int k = 0; k < 4; k++) s[mt][j][k] = 0.f;

            #pragma unroll
            for (int ks = 0; ks < 4; ks++) {
                uint32_t a[2][4], b[4][4];
                #pragma unroll
                for (int mt = 0; mt < 2; mt++)
                    ldsm4(a[mt], QT + (qRow + mt * 16) * APH + ks * 16 + qKoff);
                #pragma unroll
                for (int p = 0; p < 4; p++)
                    ldsm4(b[p], Kc + (kKey + p * 16) * APH + ks * 16 + kDoff);
                #pragma unroll
                for (int mt = 0; mt < 2; mt++)
                    #pragma unroll
                    for (int p = 0; p < 4; p++) {
                        mma_f16(s[mt][2 * p + 0], a[mt], &b[p][0]);
                        mma_f16(s[mt][2 * p + 1], a[mt], &b[p][2]);
                    }
            }

            // ---- fixed-max softmax ----
            #pragma unroll
            for (int mt = 0; mt < 2; mt++) {
                #pragma unroll
                for (int j = 0; j < 8; j++) {
                    float p0 = __expf(s[mt][j][0] - M);
                    float p1 = __expf(s[mt][j][1] - M);
                    float p2 = __expf(s[mt][j][2] - M);
                    float p3 = __expf(s[mt][j][3] - M);
                    run_s[mt][0] += p0 + p1;
                    run_s[mt][1] += p2 + p3;
                    s[mt][j][0] = p0; s[mt][j][1] = p1;
                    s[mt][j][2] = p2; s[mt][j][3] = p3;
                }
            }

            // ---- PV ----
            #pragma unroll
            for (int kk = 0; kk < 4; kk++) {
                uint32_t a[2][4];
                #pragma unroll
                for (int mt = 0; mt < 2; mt++) {
                    a[mt][0] = pack_h2(s[mt][2 * kk][0], s[mt][2 * kk][1]);
                    a[mt][1] = pack_h2(s[mt][2 * kk][2], s[mt][2 * kk][3]);
                    a[mt][2] = pack_h2(s[mt][2 * kk + 1][0], s[mt][2 * kk + 1][1]);
                    a[mt][3] = pack_h2(s[mt][2 * kk + 1][2], s[mt][2 * kk + 1][3]);
                }
                #pragma unroll
                for (int p = 0; p < 4; p++) {
                    uint32_t b[4];
                    ldsm4t(b, Vc + (kk * 16 + vKey) * APH + p * 16 + vDoff);
                    #pragma unroll
                    for (int mt = 0; mt < 2; mt++) {
                        mma_f16(oacc[mt][2 * p + 0], a[mt], &b[0]);
                        mma_f16(oacc[mt][2 * p + 1], a[mt], &b[2]);
                    }
                }
            }
        }
    }

    // ---- reduce row sums across quad ----
    #pragma unroll
    for (int mt = 0; mt < 2; mt++)
        #pragma unroll
        for (int h = 0; h < 2; h++) {
            run_s[mt][h] += __shfl_xor_sync(fullm, run_s[mt][h], 1);
            run_s[mt][h] += __shfl_xor_sync(fullm, run_s[mt][h], 2);
        }

    // ---- epilogue ----
    #pragma unroll
    for (int mt = 0; mt < 2; mt++) {
        const float inv0 = 1.f / run_s[mt][0];
        const float inv1 = 1.f / run_s[mt][1];
        #pragma unroll
        for (int d8 = 0; d8 < 8; d8++) {
            const int dcol = d8 * 8 + 2 * t;
            {
                const int srow = qt * 128 + warp * 32 + mt * 16 + g;
                *(uint32_t*)&ctx[((size_t)bb * Sc + srow) * Ec + hh * Dc + dcol] =
                    pack_h2(oacc[mt][d8][0] * inv0, oacc[mt][d8][1] * inv0);
            }
            {
                const int srow = qt * 128 + warp * 32 + mt * 16 + g + 8;
                *(uint32_t*)&ctx[((size_t)bb * Sc + srow) * Ec + hh * Dc + dcol] =
                    pack_h2(oacc[mt][d8][2] * inv1, oacc[mt][d8][3] * inv1);
            }
        }
    }
}

// ---------------------------------------------------------------------------
extern "C" void kernel_launch(void* const* d_in, const int* in_sizes, int n_in,
                              void* d_out, int out_size)
{
    const float* x_q  = (const float*)d_in[0];
    const float* x_k  = (const float*)d_in[1];
    const float* x_v  = (const float*)d_in[2];
    const float* Wq   = (const float*)d_in[3];
    const float* bq   = (const float*)d_in[4];
    const float* Wk   = (const float*)d_in[5];
    const float* bk   = (const float*)d_in[6];
    const float* Wv   = (const float*)d_in[7];
    const float* bv   = (const float*)d_in[8];
    const float* Wo   = (const float*)d_in[9];
    const float* bo   = (const float*)d_in[10];
    const float* temp = (const float*)d_in[11];
    const float* cosT = (const float*)d_in[12];
    const float* sinT = (const float*)d_in[13];
    float* out = (float*)d_out;

    __half *pQ, *pK, *pV, *pC, *cxq, *cxk, *cxv, *cwq, *cwk, *cwv, *cwo;
    cudaGetSymbolAddress((void**)&pQ, g_Q);
    cudaGetSymbolAddress((void**)&pK, g_K);
    cudaGetSymbolAddress((void**)&pV, g_V);
    cudaGetSymbolAddress((void**)&pC, g_ctx);
    cudaGetSymbolAddress((void**)&cxq, g_cxq);
    cudaGetSymbolAddress((void**)&cxk, g_cxk);
    cudaGetSymbolAddress((void**)&cxv, g_cxv);
    cudaGetSymbolAddress((void**)&cwq, g_cwq);
    cudaGetSymbolAddress((void**)&cwk, g_cwk);
    cudaGetSymbolAddress((void**)&cwv, g_cwv);
    cudaGetSymbolAddress((void**)&cwo, g_cwo);

    cudaFuncSetAttribute(gemm_qkv,
                         cudaFuncAttributeMaxDynamicSharedMemorySize, SMEM_GEMM);
    cudaFuncSetAttribute(gemm_out,
                         cudaFuncAttributeMaxDynamicSharedMemorySize, SMEM_GEMM);
    cudaFuncSetAttribute(attn_flash,
                         cudaFuncAttributeMaxDynamicSharedMemorySize, SMEM_FLASH);

    const int nx4 = Mrows * Ec / 4;   // 1M
    const int nw4 = Ec * Ec / 4;      // 256K

    cvt_all<<<dim3((nx4 + 255) / 256, 7), 256>>>(
        x_q, x_k, x_v, Wq, Wk, Wv, Wo,
        cxq, cxk, cxv, cwq, cwk, cwv, cwo, nx4, nw4);

    gemm_qkv<<<dim3(Ec / 128, Mrows / 128, 3), 128, SMEM_GEMM>>>(
        cxq, cxk, cxv, cwq, cwk, cwv, bq, bk, bv, pQ, pK, pV,
        cosT, sinT, temp);

    attn_flash<<<dim3(4, Bc * Hc), 128, SMEM_FLASH>>>(pQ, pK, pV, pC, temp);

    gemm_out<<<dim3(Ec / 128, Mrows / 128), 128, SMEM_GEMM>>>(pC, cwo, bo, out);
}